// round 3
// baseline (speedup 1.0000x reference)
#include <cuda_runtime.h>
#include <cstdint>

// ---------------- scratch (device globals; no allocation allowed) ----------
__device__ float g_h1[8192 * 5 * 30 * 30];   // conv1 pooled output
__device__ float g_h2[8192 * 1696];          // conv2 feats (1690) + ds(3) + pad(3)
__device__ float g_f1[8192 * 512];
__device__ float g_f2[8192 * 256];
__device__ float g_f3[8192 * 128];

// ---------------- conv1 + relu + maxpool ----------------
__global__ void __launch_bounds__(256) conv1_kernel(
    const float* __restrict__ x, const float* __restrict__ w1,
    const float* __restrict__ b1)
{
    __shared__ float simg[64 * 64];
    __shared__ float sw[125];
    __shared__ float sb[5];
    int b = blockIdx.x;
    int tid = threadIdx.x;
    const float* xr = x + (size_t)b * 4099 + 3;
    for (int i = tid; i < 4096; i += 256) simg[i] = xr[i];
    if (tid < 125) sw[tid] = w1[tid];
    if (tid < 5)   sb[tid] = b1[tid];
    __syncthreads();

    for (int p = tid; p < 900; p += 256) {
        int py = p / 30, px = p % 30;
        float win[6][6];
        const float* wp = &simg[(2 * py) * 64 + 2 * px];
#pragma unroll
        for (int r = 0; r < 6; r++)
#pragma unroll
            for (int c = 0; c < 6; c++)
                win[r][c] = wp[r * 64 + c];

#pragma unroll
        for (int ch = 0; ch < 5; ch++) {
            float a00 = 0.f, a01 = 0.f, a10 = 0.f, a11 = 0.f;
#pragma unroll
            for (int i = 0; i < 5; i++)
#pragma unroll
                for (int j = 0; j < 5; j++) {
                    float w = sw[ch * 25 + i * 5 + j];
                    a00 = fmaf(win[i][j],     w, a00);
                    a01 = fmaf(win[i][j + 1], w, a01);
                    a10 = fmaf(win[i + 1][j], w, a10);
                    a11 = fmaf(win[i + 1][j + 1], w, a11);
                }
            float m = fmaxf(fmaxf(a00, a01), fmaxf(a10, a11));
            float v = fmaxf(m + sb[ch], 0.f);
            g_h1[(((size_t)b * 5 + ch) * 30 + py) * 30 + px] = v;
        }
    }
}

// ---------------- conv2 + relu + maxpool + ds concat ----------------
// 2 images/block, 704 threads. Thread = (image, pooled pixel, pool row dy);
// computes the dx=0/1 pre-pool pair for all 10 oc; 2x2 max via shfl_xor(1).
__global__ void __launch_bounds__(704) conv2_kernel(
    const float* __restrict__ x, const float* __restrict__ w2,
    const float* __restrict__ b2)
{
    __shared__ float sh[2 * 4500];
    __shared__ float sw[1250];
    __shared__ float sb[10];
    int tid = threadIdx.x;
    int ib = blockIdx.x * 2;
    const float4* src = (const float4*)&g_h1[(size_t)ib * 4500];
    for (int i = tid; i < 2250; i += 704) ((float4*)sh)[i] = src[i];
    for (int i = tid; i < 1250; i += 704) sw[i] = w2[i];
    if (tid < 10) sb[tid] = b2[tid];
    __syncthreads();

    int rt = tid < 676 ? tid : 675;   // pad threads compute garbage, never store
    int il = rt / 338;
    int r  = rt % 338;
    int p  = r >> 1;                  // pooled pixel 0..168
    int dy = r & 1;                   // pool row
    int py = p / 13, px = p % 13;

    float acc[10][2];
#pragma unroll
    for (int o = 0; o < 10; o++) acc[o][0] = acc[o][1] = 0.f;

    const float* base = &sh[il * 4500];
#pragma unroll 1
    for (int ic = 0; ic < 5; ic++) {
        float win[5][6];
        const float* wp = base + ic * 900 + (2 * py + dy) * 30 + 2 * px;
#pragma unroll
        for (int i = 0; i < 5; i++)
#pragma unroll
            for (int j = 0; j < 6; j++)
                win[i][j] = wp[i * 30 + j];
#pragma unroll
        for (int oc = 0; oc < 10; oc++) {
            const float* wgt = &sw[(oc * 5 + ic) * 25];
#pragma unroll
            for (int i = 0; i < 5; i++)
#pragma unroll
                for (int j = 0; j < 5; j++) {
                    float w = wgt[i * 5 + j];
                    acc[oc][0] = fmaf(win[i][j],     w, acc[oc][0]);
                    acc[oc][1] = fmaf(win[i][j + 1], w, acc[oc][1]);
                }
        }
    }

    float* dst = &g_h2[(size_t)(ib + il) * 1696];
#pragma unroll
    for (int oc = 0; oc < 10; oc++) {
        float m = fmaxf(acc[oc][0], acc[oc][1]);
        m = fmaxf(m, __shfl_xor_sync(0xffffffffu, m, 1));   // pair over dy
        if (tid < 676 && dy == 0)
            dst[oc * 169 + p] = fmaxf(m + sb[oc], 0.f);
    }
    // ds concat (3 values per image)
    if (tid >= 676 && tid < 682) {
        int i = tid - 676;
        int jl = i / 3, j = i % 3;
        g_h2[(size_t)(ib + jl) * 1696 + 1690 + j] = x[(size_t)(ib + jl) * 4099 + j];
    }
}

// ---------------- tiled SGEMM: C = relu(A @ W^T + bias) -----------
// A:[M,K] stride lda; W:[N,K] stride ldw. VECB => ldw%4==0 and K%BK==0.
template <int BM, int BN, int BK, int TM, int TN, bool RELU, bool VECB>
__global__ void __launch_bounds__(256) gemm_bias_relu(
    const float* __restrict__ A, int lda,
    const float* __restrict__ W, int ldw,
    const float* __restrict__ bias,
    float* __restrict__ C, int ldc, int K)
{
    __shared__ float As[BK][BM + 4];
    __shared__ float Bs[BK][BN + 4];
    int tid = threadIdx.x;
    int m0 = blockIdx.x * BM;
    int n0 = blockIdx.y * BN;
    constexpr int TDM = BM / TM;
    int tidm = tid % TDM;
    int tidn = tid / TDM;

    float acc[TM][TN];
#pragma unroll
    for (int i = 0; i < TM; i++)
#pragma unroll
        for (int j = 0; j < TN; j++) acc[i][j] = 0.f;

    constexpr int A_VEC = (BM * BK) / (256 * 4);
    constexpr int B_SC  = (BN * BK) / 256;
    constexpr int B_VEC = (BN * BK) / (256 * 4);

    for (int k0 = 0; k0 < K; k0 += BK) {
#pragma unroll
        for (int v = 0; v < A_VEC; v++) {
            int idx = tid + v * 256;
            int row = idx / (BK / 4);
            int c4  = idx % (BK / 4);
            int k   = k0 + c4 * 4;
            const float* ap = &A[(size_t)(m0 + row) * lda + k];
            float4 val;
            if (VECB || k + 3 < K) {
                val = *(const float4*)ap;
            } else {
                val.x = (k + 0 < K) ? ap[0] : 0.f;
                val.y = (k + 1 < K) ? ap[1] : 0.f;
                val.z = (k + 2 < K) ? ap[2] : 0.f;
                val.w = (k + 3 < K) ? ap[3] : 0.f;
            }
            As[c4 * 4 + 0][row] = val.x;
            As[c4 * 4 + 1][row] = val.y;
            As[c4 * 4 + 2][row] = val.z;
            As[c4 * 4 + 3][row] = val.w;
        }
        if (VECB) {
#pragma unroll
            for (int v = 0; v < B_VEC; v++) {
                int idx = tid + v * 256;
                int n  = idx / (BK / 4);
                int c4 = idx % (BK / 4);
                float4 val = *(const float4*)&W[(size_t)(n0 + n) * ldw + k0 + c4 * 4];
                Bs[c4 * 4 + 0][n] = val.x;
                Bs[c4 * 4 + 1][n] = val.y;
                Bs[c4 * 4 + 2][n] = val.z;
                Bs[c4 * 4 + 3][n] = val.w;
            }
        } else {
#pragma unroll
            for (int v = 0; v < B_SC; v++) {
                int idx = tid + v * 256;
                int n = idx / BK;
                int k = idx % BK;
                float val = (k0 + k < K) ? W[(size_t)(n0 + n) * ldw + k0 + k] : 0.f;
                Bs[k][n] = val;
            }
        }
        __syncthreads();

#pragma unroll
        for (int kk = 0; kk < BK; kk++) {
            float ar[TM], br[TN];
#pragma unroll
            for (int i = 0; i < TM / 4; i++) {
                float4 v = *(const float4*)&As[kk][tidm * TM + i * 4];
                ar[i * 4] = v.x; ar[i * 4 + 1] = v.y;
                ar[i * 4 + 2] = v.z; ar[i * 4 + 3] = v.w;
            }
#pragma unroll
            for (int j = 0; j < TN / 4; j++) {
                float4 v = *(const float4*)&Bs[kk][tidn * TN + j * 4];
                br[j * 4] = v.x; br[j * 4 + 1] = v.y;
                br[j * 4 + 2] = v.z; br[j * 4 + 3] = v.w;
            }
#pragma unroll
            for (int i = 0; i < TM; i++)
#pragma unroll
                for (int j = 0; j < TN; j++)
                    acc[i][j] = fmaf(ar[i], br[j], acc[i][j]);
        }
        __syncthreads();
    }

    float bj[TN];
#pragma unroll
    for (int j = 0; j < TN; j++) bj[j] = bias[n0 + tidn * TN + j];
#pragma unroll
    for (int i = 0; i < TM; i++) {
        int row = m0 + tidm * TM + i;
#pragma unroll
        for (int j4 = 0; j4 < TN / 4; j4++) {
            float4 v;
            float v0 = acc[i][j4 * 4 + 0] + bj[j4 * 4 + 0];
            float v1 = acc[i][j4 * 4 + 1] + bj[j4 * 4 + 1];
            float v2 = acc[i][j4 * 4 + 2] + bj[j4 * 4 + 2];
            float v3 = acc[i][j4 * 4 + 3] + bj[j4 * 4 + 3];
            if (RELU) {
                v0 = fmaxf(v0, 0.f); v1 = fmaxf(v1, 0.f);
                v2 = fmaxf(v2, 0.f); v3 = fmaxf(v3, 0.f);
            }
            v.x = v0; v.y = v1; v.z = v2; v.w = v3;
            *(float4*)&C[(size_t)row * ldc + n0 + tidn * TN + j4 * 4] = v;
        }
    }
}

// ---------------- fused fc4 + fc5 + softmax + expert blend ----------------
// block = 8 samples, 256 threads.
__global__ void __launch_bounds__(256) head2_kernel(
    const float* __restrict__ fc4w, const float* __restrict__ fc4b,
    const float* __restrict__ fc5w, const float* __restrict__ fc5b,
    const float* __restrict__ Bm, const float* __restrict__ Cm,
    const float* __restrict__ x, const float* __restrict__ xt,
    float* __restrict__ out)
{
    __shared__ float s_w4[64][129];   // padded: bank-conflict-free row reads
    __shared__ float s_f3[8][128];
    __shared__ float s_h4[8][64];
    __shared__ float s_w5[16][65];    // padded
    __shared__ float s_b4[64];
    __shared__ float s_b5[16];
    __shared__ float s_A[144];
    __shared__ float s_t[3];
    int tid = threadIdx.x;
    int s0 = blockIdx.x * 8;

    // stage fc4 weights (64x128), coalesced reads, padded rows
    for (int i = tid; i < 2048; i += 256) {
        int o = i >> 5, k4 = i & 31;
        float4 v = *(const float4*)&fc4w[o * 128 + k4 * 4];
        s_w4[o][k4 * 4 + 0] = v.x; s_w4[o][k4 * 4 + 1] = v.y;
        s_w4[o][k4 * 4 + 2] = v.z; s_w4[o][k4 * 4 + 3] = v.w;
    }
    {   // stage f3 rows for the 8 samples
        int j = tid >> 5, k4 = tid & 31;
        float4 v = *(const float4*)&g_f3[(size_t)(s0 + j) * 128 + k4 * 4];
        *(float4*)&s_f3[j][k4 * 4] = v;
    }
    {   // fc5 weights 16x64 into padded rows
        int e = tid >> 4, k4 = tid & 15;
        float4 v = *(const float4*)&fc5w[e * 64 + k4 * 4];
        s_w5[e][k4 * 4 + 0] = v.x; s_w5[e][k4 * 4 + 1] = v.y;
        s_w5[e][k4 * 4 + 2] = v.z; s_w5[e][k4 * 4 + 3] = v.w;
    }
    if (tid < 64) s_b4[tid] = fc4b[tid];
    if (tid < 16) s_b5[tid] = fc5b[tid];
    if (tid < 144) s_A[tid] = Bm[tid] + Cm[tid];
    if (tid < 3)  s_t[tid] = xt[tid];
    __syncthreads();

    // fc4: warp j computes sample j's 64 outputs (2 per lane)
    {
        int j = tid >> 5, lane = tid & 31;
        float a0 = 0.f, a1 = 0.f;
#pragma unroll
        for (int k = 0; k < 128; k++) {
            float f = s_f3[j][k];
            a0 = fmaf(f, s_w4[lane][k], a0);
            a1 = fmaf(f, s_w4[lane + 32][k], a1);
        }
        s_h4[j][lane]      = fmaxf(a0 + s_b4[lane], 0.f);
        s_h4[j][lane + 32] = fmaxf(a1 + s_b4[lane + 32], 0.f);
    }
    __syncthreads();

    // fc5 + softmax + blend: thread (j,e) = sample j, expert e
    if (tid < 128) {
        int j = tid >> 4, e = tid & 15;
        float lg = s_b5[e];
#pragma unroll
        for (int k = 0; k < 64; k++)
            lg = fmaf(s_h4[j][k], s_w5[e][k], lg);
        float mx = lg;
#pragma unroll
        for (int m = 8; m; m >>= 1)
            mx = fmaxf(mx, __shfl_xor_sync(0xffffffffu, mx, m));
        float pe = expf(lg - mx);
        float sum = pe;
#pragma unroll
        for (int m = 8; m; m >>= 1)
            sum += __shfl_xor_sync(0xffffffffu, sum, m);
        float w = pe / sum;

        int s = s0 + j;
        float d0 = s_t[0] - x[(size_t)s * 4099 + 0];
        float d1 = s_t[1] - x[(size_t)s * 4099 + 1];
        float d2 = s_t[2] - x[(size_t)s * 4099 + 2];
        const float* A = &s_A[e * 9];
        float o0 = w * (A[0] * d0 + A[1] * d1 + A[2] * d2);
        float o1 = w * (A[3] * d0 + A[4] * d1 + A[5] * d2);
        float o2 = w * (A[6] * d0 + A[7] * d1 + A[8] * d2);
#pragma unroll
        for (int m = 8; m; m >>= 1) {
            o0 += __shfl_xor_sync(0xffffffffu, o0, m);
            o1 += __shfl_xor_sync(0xffffffffu, o1, m);
            o2 += __shfl_xor_sync(0xffffffffu, o2, m);
        }
        if (e == 0) {
            out[(size_t)s * 3 + 0] = o0;
            out[(size_t)s * 3 + 1] = o1;
            out[(size_t)s * 3 + 2] = o2;
        }
    }
}

// ---------------- launch ----------------
extern "C" void kernel_launch(void* const* d_in, const int* in_sizes, int n_in,
                              void* d_out, int out_size)
{
    const float* x    = (const float*)d_in[0];
    const float* w1   = (const float*)d_in[1];
    const float* b1   = (const float*)d_in[2];
    const float* w2   = (const float*)d_in[3];
    const float* b2   = (const float*)d_in[4];
    const float* fc1w = (const float*)d_in[5];
    const float* fc1b = (const float*)d_in[6];
    const float* fc2w = (const float*)d_in[7];
    const float* fc2b = (const float*)d_in[8];
    const float* fc3w = (const float*)d_in[9];
    const float* fc3b = (const float*)d_in[10];
    const float* fc4w = (const float*)d_in[11];
    const float* fc4b = (const float*)d_in[12];
    const float* fc5w = (const float*)d_in[13];
    const float* fc5b = (const float*)d_in[14];
    const float* Bm   = (const float*)d_in[15];
    const float* Cm   = (const float*)d_in[16];
    const float* xt   = (const float*)d_in[17];

    int B = in_sizes[0] / 4099;  // 8192

    float *h2, *f1, *f2, *f3;
    cudaGetSymbolAddress((void**)&h2, g_h2);
    cudaGetSymbolAddress((void**)&f1, g_f1);
    cudaGetSymbolAddress((void**)&f2, g_f2);
    cudaGetSymbolAddress((void**)&f3, g_f3);

    conv1_kernel<<<B, 256>>>(x, w1, b1);
    conv2_kernel<<<B / 2, 704>>>(x, w2, b2);

    gemm_bias_relu<128, 64, 16, 8, 4, true, false>
        <<<dim3(B / 128, 512 / 64), 256>>>(h2, 1696, fc1w, 1693, fc1b, f1, 512, 1693);
    gemm_bias_relu<128, 64, 16, 8, 4, true, true>
        <<<dim3(B / 128, 256 / 64), 256>>>(f1, 512, fc2w, 512, fc2b, f2, 256, 512);
    gemm_bias_relu<64, 64, 16, 4, 4, true, true>
        <<<dim3(B / 64, 128 / 64), 256>>>(f2, 256, fc3w, 256, fc3b, f3, 128, 256);

    head2_kernel<<<B / 8, 256>>>(fc4w, fc4b, fc5w, fc5b, Bm, Cm, x, xt, (float*)d_out);
}

// round 6
// speedup vs baseline: 1.2553x; 1.2553x over previous
#include <cuda_runtime.h>
#include <cstdint>

// ---------------- scratch (device globals; no allocation allowed) ----------
__device__ float g_h1[8192 * 5 * 30 * 30];   // conv1 pooled output
__device__ float g_h2[8192 * 1696];          // conv2 feats(1690)+ds(3)+zeropad(3)
__device__ float g_w1p[512 * 1696];          // fc1 weights repacked, K padded
__device__ float g_f1[8192 * 512];
__device__ float g_f2[8192 * 256];
__device__ float g_f3[8192 * 128];

// ---------------- conv1 + relu + maxpool ----------------
__global__ void __launch_bounds__(256) conv1_kernel(
    const float* __restrict__ x, const float* __restrict__ w1,
    const float* __restrict__ b1)
{
    __shared__ float simg[64 * 64];
    __shared__ float sw[125];
    __shared__ float sb[5];
    int b = blockIdx.x;
    int tid = threadIdx.x;
    const float* xr = x + (size_t)b * 4099 + 3;
    for (int i = tid; i < 4096; i += 256) simg[i] = xr[i];
    if (tid < 125) sw[tid] = w1[tid];
    if (tid < 5)   sb[tid] = b1[tid];
    __syncthreads();

    for (int p = tid; p < 900; p += 256) {
        int py = p / 30, px = p % 30;
        float win[6][6];
        const float* wp = &simg[(2 * py) * 64 + 2 * px];
#pragma unroll
        for (int r = 0; r < 6; r++)
#pragma unroll
            for (int c = 0; c < 6; c++)
                win[r][c] = wp[r * 64 + c];

#pragma unroll
        for (int ch = 0; ch < 5; ch++) {
            float a00 = 0.f, a01 = 0.f, a10 = 0.f, a11 = 0.f;
#pragma unroll
            for (int i = 0; i < 5; i++)
#pragma unroll
                for (int j = 0; j < 5; j++) {
                    float w = sw[ch * 25 + i * 5 + j];
                    a00 = fmaf(win[i][j],     w, a00);
                    a01 = fmaf(win[i][j + 1], w, a01);
                    a10 = fmaf(win[i + 1][j], w, a10);
                    a11 = fmaf(win[i + 1][j + 1], w, a11);
                }
            float m = fmaxf(fmaxf(a00, a01), fmaxf(a10, a11));
            float v = fmaxf(m + sb[ch], 0.f);
            g_h1[(((size_t)b * 5 + ch) * 30 + py) * 30 + px] = v;
        }
    }
}

// ---------------- conv2 + relu + maxpool + ds concat (R2 version) ---------
__global__ void __launch_bounds__(352) conv2_kernel(
    const float* __restrict__ x, const float* __restrict__ w2,
    const float* __restrict__ b2)
{
    __shared__ float sh[2 * 4500];
    __shared__ float sw[1250];
    __shared__ float sb[10];
    int tid = threadIdx.x;
    int ib = blockIdx.x * 2;
    const float* src = &g_h1[(size_t)ib * 4500];
    for (int i = tid; i < 9000; i += 352) sh[i] = src[i];
    for (int i = tid; i < 1250; i += 352) sw[i] = w2[i];
    if (tid < 10) sb[tid] = b2[tid];
    __syncthreads();

    if (tid < 338) {
        int il = tid / 169;
        int p  = tid % 169;
        int b  = ib + il;
        int py = p / 13, px = p % 13;
        float acc[10][4];
#pragma unroll
        for (int o = 0; o < 10; o++)
            acc[o][0] = acc[o][1] = acc[o][2] = acc[o][3] = 0.f;
        const float* base = &sh[il * 4500];
#pragma unroll 1
        for (int ic = 0; ic < 5; ic++) {
            float win[6][6];
            const float* wp = base + ic * 900 + (2 * py) * 30 + 2 * px;
#pragma unroll
            for (int r = 0; r < 6; r++)
#pragma unroll
                for (int c = 0; c < 6; c++)
                    win[r][c] = wp[r * 30 + c];
#pragma unroll
            for (int oc = 0; oc < 10; oc++) {
                const float* wgt = &sw[(oc * 5 + ic) * 25];
#pragma unroll
                for (int i = 0; i < 5; i++)
#pragma unroll
                    for (int j = 0; j < 5; j++) {
                        float w = wgt[i * 5 + j];
                        acc[oc][0] = fmaf(win[i][j],         w, acc[oc][0]);
                        acc[oc][1] = fmaf(win[i][j + 1],     w, acc[oc][1]);
                        acc[oc][2] = fmaf(win[i + 1][j],     w, acc[oc][2]);
                        acc[oc][3] = fmaf(win[i + 1][j + 1], w, acc[oc][3]);
                    }
            }
        }
        float* dst = &g_h2[(size_t)b * 1696];
#pragma unroll
        for (int oc = 0; oc < 10; oc++) {
            float m = fmaxf(fmaxf(acc[oc][0], acc[oc][1]),
                            fmaxf(acc[oc][2], acc[oc][3]));
            dst[oc * 169 + p] = fmaxf(m + sb[oc], 0.f);
        }
    } else if (tid < 338 + 12) {
        // ds concat (3 values) + zero pad (3 values) per image
        int i = tid - 338;
        int il = i / 6, j = i % 6;
        int b = ib + il;
        g_h2[(size_t)b * 1696 + 1690 + j] =
            (j < 3) ? x[(size_t)b * 4099 + j] : 0.f;
    }
}

// ---------------- fc1 weight repack: [512,1693] -> [512,1696] zero-pad ----
__global__ void __launch_bounds__(256) repack_fc1(const float* __restrict__ w)
{
    int idx = blockIdx.x * 256 + threadIdx.x;   // 512*1696 total
    int n = idx / 1696, k = idx % 1696;
    g_w1p[idx] = (k < 1693) ? w[n * 1693 + k] : 0.f;
}

// ---------------- double-buffered SGEMM: C = relu(A @ W^T + bias) --------
// BM=BN=128, BK=16, TM=TN=8, 256 threads. Requires: M%128==0, N%128==0,
// K%16==0, lda%4==0, ldw%4==0 (all rows 16B aligned).
template <bool RELU>
__global__ void __launch_bounds__(256) gemm128_db(
    const float* __restrict__ A, int lda,
    const float* __restrict__ W, int ldw,
    const float* __restrict__ bias,
    float* __restrict__ C, int ldc, int K)
{
    __shared__ float As[2][16][132];
    __shared__ float Bs[2][16][132];
    int tid = threadIdx.x;
    int m0 = blockIdx.x * 128;
    int n0 = blockIdx.y * 128;
    int tidm = tid % 16;
    int tidn = tid / 16;

    // staging-load mapping: thread handles rows (tid>>2) and (tid>>2)+64,
    // float4 column (tid&3) of the 128x16 tile
    int lrow = tid >> 2;
    int lc4  = tid & 3;
    const float* aptr0 = A + (size_t)(m0 + lrow) * lda + lc4 * 4;
    const float* aptr1 = aptr0 + (size_t)64 * lda;
    const float* bptr0 = W + (size_t)(n0 + lrow) * ldw + lc4 * 4;
    const float* bptr1 = bptr0 + (size_t)64 * ldw;

    float acc[8][8];
#pragma unroll
    for (int i = 0; i < 8; i++)
#pragma unroll
        for (int j = 0; j < 8; j++) acc[i][j] = 0.f;

    float4 a0, a1, b0, b1;
    // prologue: load tile 0
    a0 = *(const float4*)(aptr0);
    a1 = *(const float4*)(aptr1);
    b0 = *(const float4*)(bptr0);
    b1 = *(const float4*)(bptr1);
    {
        float* s = &As[0][lc4 * 4][0];
        s[0 * 132 + lrow] = a0.x; s[1 * 132 + lrow] = a0.y;
        s[2 * 132 + lrow] = a0.z; s[3 * 132 + lrow] = a0.w;
        s[0 * 132 + lrow + 64] = a1.x; s[1 * 132 + lrow + 64] = a1.y;
        s[2 * 132 + lrow + 64] = a1.z; s[3 * 132 + lrow + 64] = a1.w;
        float* t = &Bs[0][lc4 * 4][0];
        t[0 * 132 + lrow] = b0.x; t[1 * 132 + lrow] = b0.y;
        t[2 * 132 + lrow] = b0.z; t[3 * 132 + lrow] = b0.w;
        t[0 * 132 + lrow + 64] = b1.x; t[1 * 132 + lrow + 64] = b1.y;
        t[2 * 132 + lrow + 64] = b1.z; t[3 * 132 + lrow + 64] = b1.w;
    }
    __syncthreads();

    int ntiles = K / 16;
    for (int t = 0; t < ntiles; t++) {
        int cur = t & 1;
        bool more = (t + 1) < ntiles;
        if (more) {
            int koff = (t + 1) * 16;
            a0 = *(const float4*)(aptr0 + koff);
            a1 = *(const float4*)(aptr1 + koff);
            b0 = *(const float4*)(bptr0 + koff);
            b1 = *(const float4*)(bptr1 + koff);
        }
#pragma unroll
        for (int kk = 0; kk < 16; kk++) {
            float ar[8], br[8];
            float4 v;
            v = *(const float4*)&As[cur][kk][tidm * 8];
            ar[0] = v.x; ar[1] = v.y; ar[2] = v.z; ar[3] = v.w;
            v = *(const float4*)&As[cur][kk][tidm * 8 + 4];
            ar[4] = v.x; ar[5] = v.y; ar[6] = v.z; ar[7] = v.w;
            v = *(const float4*)&Bs[cur][kk][tidn * 8];
            br[0] = v.x; br[1] = v.y; br[2] = v.z; br[3] = v.w;
            v = *(const float4*)&Bs[cur][kk][tidn * 8 + 4];
            br[4] = v.x; br[5] = v.y; br[6] = v.z; br[7] = v.w;
#pragma unroll
            for (int i = 0; i < 8; i++)
#pragma unroll
                for (int j = 0; j < 8; j++)
                    acc[i][j] = fmaf(ar[i], br[j], acc[i][j]);
        }
        if (more) {
            int nxt = cur ^ 1;
            float* s = &As[nxt][lc4 * 4][0];
            s[0 * 132 + lrow] = a0.x; s[1 * 132 + lrow] = a0.y;
            s[2 * 132 + lrow] = a0.z; s[3 * 132 + lrow] = a0.w;
            s[0 * 132 + lrow + 64] = a1.x; s[1 * 132 + lrow + 64] = a1.y;
            s[2 * 132 + lrow + 64] = a1.z; s[3 * 132 + lrow + 64] = a1.w;
            float* u = &Bs[nxt][lc4 * 4][0];
            u[0 * 132 + lrow] = b0.x; u[1 * 132 + lrow] = b0.y;
            u[2 * 132 + lrow] = b0.z; u[3 * 132 + lrow] = b0.w;
            u[0 * 132 + lrow + 64] = b1.x; u[1 * 132 + lrow + 64] = b1.y;
            u[2 * 132 + lrow + 64] = b1.z; u[3 * 132 + lrow + 64] = b1.w;
            __syncthreads();
        }
    }

    float bj[8];
#pragma unroll
    for (int j = 0; j < 8; j++) bj[j] = bias[n0 + tidn * 8 + j];
#pragma unroll
    for (int i = 0; i < 8; i++) {
        int row = m0 + tidm * 8 + i;
#pragma unroll
        for (int j4 = 0; j4 < 2; j4++) {
            float v0 = acc[i][j4 * 4 + 0] + bj[j4 * 4 + 0];
            float v1 = acc[i][j4 * 4 + 1] + bj[j4 * 4 + 1];
            float v2 = acc[i][j4 * 4 + 2] + bj[j4 * 4 + 2];
            float v3 = acc[i][j4 * 4 + 3] + bj[j4 * 4 + 3];
            if (RELU) {
                v0 = fmaxf(v0, 0.f); v1 = fmaxf(v1, 0.f);
                v2 = fmaxf(v2, 0.f); v3 = fmaxf(v3, 0.f);
            }
            float4 v = {v0, v1, v2, v3};
            *(float4*)&C[(size_t)row * ldc + n0 + tidn * 8 + j4 * 4] = v;
        }
    }
}

// ---------------- fused fc4 + fc5 + softmax + expert blend ----------------
__global__ void __launch_bounds__(256) head2_kernel(
    const float* __restrict__ fc4w, const float* __restrict__ fc4b,
    const float* __restrict__ fc5w, const float* __restrict__ fc5b,
    const float* __restrict__ Bm, const float* __restrict__ Cm,
    const float* __restrict__ x, const float* __restrict__ xt,
    float* __restrict__ out)
{
    __shared__ float s_w4[64][129];
    __shared__ float s_f3[8][128];
    __shared__ float s_h4[8][64];
    __shared__ float s_w5[16][65];
    __shared__ float s_b4[64];
    __shared__ float s_b5[16];
    __shared__ float s_A[144];
    __shared__ float s_t[3];
    int tid = threadIdx.x;
    int s0 = blockIdx.x * 8;

    for (int i = tid; i < 2048; i += 256) {
        int o = i >> 5, k4 = i & 31;
        float4 v = *(const float4*)&fc4w[o * 128 + k4 * 4];
        s_w4[o][k4 * 4 + 0] = v.x; s_w4[o][k4 * 4 + 1] = v.y;
        s_w4[o][k4 * 4 + 2] = v.z; s_w4[o][k4 * 4 + 3] = v.w;
    }
    {
        int j = tid >> 5, k4 = tid & 31;
        float4 v = *(const float4*)&g_f3[(size_t)(s0 + j) * 128 + k4 * 4];
        *(float4*)&s_f3[j][k4 * 4] = v;
    }
    {
        int e = tid >> 4, k4 = tid & 15;
        float4 v = *(const float4*)&fc5w[e * 64 + k4 * 4];
        s_w5[e][k4 * 4 + 0] = v.x; s_w5[e][k4 * 4 + 1] = v.y;
        s_w5[e][k4 * 4 + 2] = v.z; s_w5[e][k4 * 4 + 3] = v.w;
    }
    if (tid < 64) s_b4[tid] = fc4b[tid];
    if (tid < 16) s_b5[tid] = fc5b[tid];
    if (tid < 144) s_A[tid] = Bm[tid] + Cm[tid];
    if (tid < 3)  s_t[tid] = xt[tid];
    __syncthreads();

    {
        int j = tid >> 5, lane = tid & 31;
        float a0 = 0.f, a1 = 0.f;
#pragma unroll
        for (int k = 0; k < 128; k++) {
            float f = s_f3[j][k];
            a0 = fmaf(f, s_w4[lane][k], a0);
            a1 = fmaf(f, s_w4[lane + 32][k], a1);
        }
        s_h4[j][lane]      = fmaxf(a0 + s_b4[lane], 0.f);
        s_h4[j][lane + 32] = fmaxf(a1 + s_b4[lane + 32], 0.f);
    }
    __syncthreads();

    if (tid < 128) {
        int j = tid >> 4, e = tid & 15;
        float lg = s_b5[e];
#pragma unroll
        for (int k = 0; k < 64; k++)
            lg = fmaf(s_h4[j][k], s_w5[e][k], lg);
        float mx = lg;
#pragma unroll
        for (int m = 8; m; m >>= 1)
            mx = fmaxf(mx, __shfl_xor_sync(0xffffffffu, mx, m));
        float pe = expf(lg - mx);
        float sum = pe;
#pragma unroll
        for (int m = 8; m; m >>= 1)
            sum += __shfl_xor_sync(0xffffffffu, sum, m);
        float w = pe / sum;

        int s = s0 + j;
        float d0 = s_t[0] - x[(size_t)s * 4099 + 0];
        float d1 = s_t[1] - x[(size_t)s * 4099 + 1];
        float d2 = s_t[2] - x[(size_t)s * 4099 + 2];
        const float* A = &s_A[e * 9];
        float o0 = w * (A[0] * d0 + A[1] * d1 + A[2] * d2);
        float o1 = w * (A[3] * d0 + A[4] * d1 + A[5] * d2);
        float o2 = w * (A[6] * d0 + A[7] * d1 + A[8] * d2);
#pragma unroll
        for (int m = 8; m; m >>= 1) {
            o0 += __shfl_xor_sync(0xffffffffu, o0, m);
            o1 += __shfl_xor_sync(0xffffffffu, o1, m);
            o2 += __shfl_xor_sync(0xffffffffu, o2, m);
        }
        if (e == 0) {
            out[(size_t)s * 3 + 0] = o0;
            out[(size_t)s * 3 + 1] = o1;
            out[(size_t)s * 3 + 2] = o2;
        }
    }
}

// ---------------- launch ----------------
extern "C" void kernel_launch(void* const* d_in, const int* in_sizes, int n_in,
                              void* d_out, int out_size)
{
    const float* x    = (const float*)d_in[0];
    const float* w1   = (const float*)d_in[1];
    const float* b1   = (const float*)d_in[2];
    const float* w2   = (const float*)d_in[3];
    const float* b2   = (const float*)d_in[4];
    const float* fc1w = (const float*)d_in[5];
    const float* fc1b = (const float*)d_in[6];
    const float* fc2w = (const float*)d_in[7];
    const float* fc2b = (const float*)d_in[8];
    const float* fc3w = (const float*)d_in[9];
    const float* fc3b = (const float*)d_in[10];
    const float* fc4w = (const float*)d_in[11];
    const float* fc4b = (const float*)d_in[12];
    const float* fc5w = (const float*)d_in[13];
    const float* fc5b = (const float*)d_in[14];
    const float* Bm   = (const float*)d_in[15];
    const float* Cm   = (const float*)d_in[16];
    const float* xt   = (const float*)d_in[17];

    int B = in_sizes[0] / 4099;  // 8192

    float *h2, *w1p, *f1, *f2, *f3;
    cudaGetSymbolAddress((void**)&h2,  g_h2);
    cudaGetSymbolAddress((void**)&w1p, g_w1p);
    cudaGetSymbolAddress((void**)&f1,  g_f1);
    cudaGetSymbolAddress((void**)&f2,  g_f2);
    cudaGetSymbolAddress((void**)&f3,  g_f3);

    conv1_kernel<<<B, 256>>>(x, w1, b1);
    repack_fc1<<<(512 * 1696) / 256, 256>>>(fc1w);
    conv2_kernel<<<B / 2, 352>>>(x, w2, b2);

    gemm128_db<true><<<dim3(B / 128, 4), 256>>>(h2, 1696, w1p, 1696, fc1b, f1, 512, 1696);
    gemm128_db<true><<<dim3(B / 128, 2), 256>>>(f1, 512, fc2w, 512, fc2b, f2, 256, 512);
    gemm128_db<true><<<dim3(B / 128, 1), 256>>>(f2, 256, fc3w, 256, fc3b, f3, 128, 256);

    head2_kernel<<<B / 8, 256>>>(fc4w, fc4b, fc5w, fc5b, Bm, Cm, x, xt, (float*)d_out);
}

// round 7
// speedup vs baseline: 1.3430x; 1.0699x over previous
#include <cuda_runtime.h>
#include <cstdint>

// ---------------- scratch (device globals; no allocation allowed) ----------
__device__ float g_h2[8192 * 1696];          // conv2 feats(1690)+ds(3)+zeropad(3)
__device__ float g_w1p[512 * 1696];          // fc1 weights repacked, K padded
__device__ float g_f1[8192 * 512];
__device__ float g_f2[8192 * 256];
__device__ float g_f3[8192 * 128];

// ---------------- fused conv1+pool+conv2+pool+concat ----------------
// one image per block, 384 threads. conv1 result lives in smem only.
__global__ void __launch_bounds__(384) fused_conv_kernel(
    const float* __restrict__ x,
    const float* __restrict__ w1, const float* __restrict__ b1,
    const float* __restrict__ w2, const float* __restrict__ b2)
{
    __shared__ float simg[64 * 64];      // 16 KB
    __shared__ float sh1[5 * 900];       // 18 KB conv1 pooled output
    __shared__ float sw1[125];
    __shared__ float sw2[1250];
    __shared__ float sb1[5];
    __shared__ float sb2[10];
    int b = blockIdx.x;
    int tid = threadIdx.x;

    const float* xr = x + (size_t)b * 4099 + 3;
    for (int i = tid; i < 4096; i += 384) simg[i] = xr[i];
    for (int i = tid; i < 1250; i += 384) sw2[i] = w2[i];
    if (tid < 125) sw1[tid] = w1[tid];
    if (tid < 5)   sb1[tid] = b1[tid];
    if (tid < 10)  sb2[tid] = b2[tid];
    __syncthreads();

    // ---- phase B: conv1 + relu + maxpool -> sh1[ch*900 + py*30 + px]
    for (int p = tid; p < 900; p += 384) {
        int py = p / 30, px = p % 30;
        float win[6][6];
        const float* wp = &simg[(2 * py) * 64 + 2 * px];
#pragma unroll
        for (int r = 0; r < 6; r++)
#pragma unroll
            for (int c = 0; c < 6; c++)
                win[r][c] = wp[r * 64 + c];

#pragma unroll
        for (int ch = 0; ch < 5; ch++) {
            float a00 = 0.f, a01 = 0.f, a10 = 0.f, a11 = 0.f;
#pragma unroll
            for (int i = 0; i < 5; i++)
#pragma unroll
                for (int j = 0; j < 5; j++) {
                    float w = sw1[ch * 25 + i * 5 + j];
                    a00 = fmaf(win[i][j],         w, a00);
                    a01 = fmaf(win[i][j + 1],     w, a01);
                    a10 = fmaf(win[i + 1][j],     w, a10);
                    a11 = fmaf(win[i + 1][j + 1], w, a11);
                }
            float m = fmaxf(fmaxf(a00, a01), fmaxf(a10, a11));
            sh1[ch * 900 + p] = fmaxf(m + sb1[ch], 0.f);
        }
    }
    __syncthreads();

    // ---- phase C: conv2 + relu + maxpool, oc split into two halves
    if (tid < 338) {
        int half = tid / 169;            // 0 -> oc 0..4, 1 -> oc 5..9
        int p    = tid % 169;
        int py = p / 13, px = p % 13;
        float acc[5][4];
#pragma unroll
        for (int o = 0; o < 5; o++)
            acc[o][0] = acc[o][1] = acc[o][2] = acc[o][3] = 0.f;

#pragma unroll 1
        for (int ic = 0; ic < 5; ic++) {
            float win[6][6];
            const float* wp = &sh1[ic * 900 + (2 * py) * 30 + 2 * px];
#pragma unroll
            for (int r = 0; r < 6; r++)
#pragma unroll
                for (int c = 0; c < 6; c++)
                    win[r][c] = wp[r * 30 + c];
#pragma unroll
            for (int o = 0; o < 5; o++) {
                const float* wgt = &sw2[((half * 5 + o) * 5 + ic) * 25];
#pragma unroll
                for (int i = 0; i < 5; i++)
#pragma unroll
                    for (int j = 0; j < 5; j++) {
                        float w = wgt[i * 5 + j];
                        acc[o][0] = fmaf(win[i][j],         w, acc[o][0]);
                        acc[o][1] = fmaf(win[i][j + 1],     w, acc[o][1]);
                        acc[o][2] = fmaf(win[i + 1][j],     w, acc[o][2]);
                        acc[o][3] = fmaf(win[i + 1][j + 1], w, acc[o][3]);
                    }
            }
        }
        float* dst = &g_h2[(size_t)b * 1696];
#pragma unroll
        for (int o = 0; o < 5; o++) {
            int oc = half * 5 + o;
            float m = fmaxf(fmaxf(acc[o][0], acc[o][1]),
                            fmaxf(acc[o][2], acc[o][3]));
            dst[oc * 169 + p] = fmaxf(m + sb2[oc], 0.f);
        }
    } else if (tid < 338 + 6) {
        // ds concat (3) + zero pad (3)
        int j = tid - 338;
        g_h2[(size_t)b * 1696 + 1690 + j] =
            (j < 3) ? x[(size_t)b * 4099 + j] : 0.f;
    }
}

// ---------------- fc1 weight repack: [512,1693] -> [512,1696] zero-pad ----
__global__ void __launch_bounds__(256) repack_fc1(const float* __restrict__ w)
{
    int idx = blockIdx.x * 256 + threadIdx.x;   // 512*1696 total
    int n = idx / 1696, k = idx % 1696;
    g_w1p[idx] = (k < 1693) ? w[n * 1693 + k] : 0.f;
}

// ---------------- double-buffered SGEMM: C = relu(A @ W^T + bias) --------
// BM=BN=128, BK=16, TM=TN=8, 256 threads; global AND fragment double-buffer.
// Requires: M%128==0, N%128==0, K%16==0, rows 16B aligned.
template <bool RELU>
__global__ void __launch_bounds__(256) gemm128_db(
    const float* __restrict__ A, int lda,
    const float* __restrict__ W, int ldw,
    const float* __restrict__ bias,
    float* __restrict__ C, int ldc, int K)
{
    __shared__ float As[2][16][132];
    __shared__ float Bs[2][16][132];
    int tid = threadIdx.x;
    int m0 = blockIdx.x * 128;
    int n0 = blockIdx.y * 128;
    int tidm = tid % 16;
    int tidn = tid / 16;

    int lrow = tid >> 2;
    int lc4  = tid & 3;
    const float* aptr0 = A + (size_t)(m0 + lrow) * lda + lc4 * 4;
    const float* aptr1 = aptr0 + (size_t)64 * lda;
    const float* bptr0 = W + (size_t)(n0 + lrow) * ldw + lc4 * 4;
    const float* bptr1 = bptr0 + (size_t)64 * ldw;

    float acc[8][8];
#pragma unroll
    for (int i = 0; i < 8; i++)
#pragma unroll
        for (int j = 0; j < 8; j++) acc[i][j] = 0.f;

    float4 a0, a1, b0, b1;
    a0 = *(const float4*)(aptr0);
    a1 = *(const float4*)(aptr1);
    b0 = *(const float4*)(bptr0);
    b1 = *(const float4*)(bptr1);
    {
        float* s = &As[0][lc4 * 4][0];
        s[0 * 132 + lrow] = a0.x; s[1 * 132 + lrow] = a0.y;
        s[2 * 132 + lrow] = a0.z; s[3 * 132 + lrow] = a0.w;
        s[0 * 132 + lrow + 64] = a1.x; s[1 * 132 + lrow + 64] = a1.y;
        s[2 * 132 + lrow + 64] = a1.z; s[3 * 132 + lrow + 64] = a1.w;
        float* t = &Bs[0][lc4 * 4][0];
        t[0 * 132 + lrow] = b0.x; t[1 * 132 + lrow] = b0.y;
        t[2 * 132 + lrow] = b0.z; t[3 * 132 + lrow] = b0.w;
        t[0 * 132 + lrow + 64] = b1.x; t[1 * 132 + lrow + 64] = b1.y;
        t[2 * 132 + lrow + 64] = b1.z; t[3 * 132 + lrow + 64] = b1.w;
    }
    __syncthreads();

    int ntiles = K / 16;
    for (int t = 0; t < ntiles; t++) {
        int cur = t & 1;
        bool more = (t + 1) < ntiles;
        if (more) {
            int koff = (t + 1) * 16;
            a0 = *(const float4*)(aptr0 + koff);
            a1 = *(const float4*)(aptr1 + koff);
            b0 = *(const float4*)(bptr0 + koff);
            b1 = *(const float4*)(bptr1 + koff);
        }
        // fragment double-buffer over kk
        float ar[2][8], br[2][8];
        {
            float4 v;
            v = *(const float4*)&As[cur][0][tidm * 8];
            ar[0][0] = v.x; ar[0][1] = v.y; ar[0][2] = v.z; ar[0][3] = v.w;
            v = *(const float4*)&As[cur][0][tidm * 8 + 4];
            ar[0][4] = v.x; ar[0][5] = v.y; ar[0][6] = v.z; ar[0][7] = v.w;
            v = *(const float4*)&Bs[cur][0][tidn * 8];
            br[0][0] = v.x; br[0][1] = v.y; br[0][2] = v.z; br[0][3] = v.w;
            v = *(const float4*)&Bs[cur][0][tidn * 8 + 4];
            br[0][4] = v.x; br[0][5] = v.y; br[0][6] = v.z; br[0][7] = v.w;
        }
#pragma unroll
        for (int kk = 0; kk < 16; kk++) {
            int c = kk & 1, n = c ^ 1;
            if (kk < 15) {
                float4 v;
                v = *(const float4*)&As[cur][kk + 1][tidm * 8];
                ar[n][0] = v.x; ar[n][1] = v.y; ar[n][2] = v.z; ar[n][3] = v.w;
                v = *(const float4*)&As[cur][kk + 1][tidm * 8 + 4];
                ar[n][4] = v.x; ar[n][5] = v.y; ar[n][6] = v.z; ar[n][7] = v.w;
                v = *(const float4*)&Bs[cur][kk + 1][tidn * 8];
                br[n][0] = v.x; br[n][1] = v.y; br[n][2] = v.z; br[n][3] = v.w;
                v = *(const float4*)&Bs[cur][kk + 1][tidn * 8 + 4];
                br[n][4] = v.x; br[n][5] = v.y; br[n][6] = v.z; br[n][7] = v.w;
            }
#pragma unroll
            for (int i = 0; i < 8; i++)
#pragma unroll
                for (int j = 0; j < 8; j++)
                    acc[i][j] = fmaf(ar[c][i], br[c][j], acc[i][j]);
        }
        if (more) {
            int nxt = cur ^ 1;
            float* s = &As[nxt][lc4 * 4][0];
            s[0 * 132 + lrow] = a0.x; s[1 * 132 + lrow] = a0.y;
            s[2 * 132 + lrow] = a0.z; s[3 * 132 + lrow] = a0.w;
            s[0 * 132 + lrow + 64] = a1.x; s[1 * 132 + lrow + 64] = a1.y;
            s[2 * 132 + lrow + 64] = a1.z; s[3 * 132 + lrow + 64] = a1.w;
            float* u = &Bs[nxt][lc4 * 4][0];
            u[0 * 132 + lrow] = b0.x; u[1 * 132 + lrow] = b0.y;
            u[2 * 132 + lrow] = b0.z; u[3 * 132 + lrow] = b0.w;
            u[0 * 132 + lrow + 64] = b1.x; u[1 * 132 + lrow + 64] = b1.y;
            u[2 * 132 + lrow + 64] = b1.z; u[3 * 132 + lrow + 64] = b1.w;
            __syncthreads();
        }
    }

    float bj[8];
#pragma unroll
    for (int j = 0; j < 8; j++) bj[j] = bias[n0 + tidn * 8 + j];
#pragma unroll
    for (int i = 0; i < 8; i++) {
        int row = m0 + tidm * 8 + i;
#pragma unroll
        for (int j4 = 0; j4 < 2; j4++) {
            float v0 = acc[i][j4 * 4 + 0] + bj[j4 * 4 + 0];
            float v1 = acc[i][j4 * 4 + 1] + bj[j4 * 4 + 1];
            float v2 = acc[i][j4 * 4 + 2] + bj[j4 * 4 + 2];
            float v3 = acc[i][j4 * 4 + 3] + bj[j4 * 4 + 3];
            if (RELU) {
                v0 = fmaxf(v0, 0.f); v1 = fmaxf(v1, 0.f);
                v2 = fmaxf(v2, 0.f); v3 = fmaxf(v3, 0.f);
            }
            float4 v = {v0, v1, v2, v3};
            *(float4*)&C[(size_t)row * ldc + n0 + tidn * 8 + j4 * 4] = v;
        }
    }
}

// ---------------- fused fc4 + fc5 + softmax + expert blend ----------------
__global__ void __launch_bounds__(256) head2_kernel(
    const float* __restrict__ fc4w, const float* __restrict__ fc4b,
    const float* __restrict__ fc5w, const float* __restrict__ fc5b,
    const float* __restrict__ Bm, const float* __restrict__ Cm,
    const float* __restrict__ x, const float* __restrict__ xt,
    float* __restrict__ out)
{
    __shared__ float s_w4[64][129];
    __shared__ float s_f3[8][128];
    __shared__ float s_h4[8][64];
    __shared__ float s_w5[16][65];
    __shared__ float s_b4[64];
    __shared__ float s_b5[16];
    __shared__ float s_A[144];
    __shared__ float s_t[3];
    int tid = threadIdx.x;
    int s0 = blockIdx.x * 8;

    for (int i = tid; i < 2048; i += 256) {
        int o = i >> 5, k4 = i & 31;
        float4 v = *(const float4*)&fc4w[o * 128 + k4 * 4];
        s_w4[o][k4 * 4 + 0] = v.x; s_w4[o][k4 * 4 + 1] = v.y;
        s_w4[o][k4 * 4 + 2] = v.z; s_w4[o][k4 * 4 + 3] = v.w;
    }
    {
        int j = tid >> 5, k4 = tid & 31;
        float4 v = *(const float4*)&g_f3[(size_t)(s0 + j) * 128 + k4 * 4];
        *(float4*)&s_f3[j][k4 * 4] = v;
    }
    {
        int e = tid >> 4, k4 = tid & 15;
        float4 v = *(const float4*)&fc5w[e * 64 + k4 * 4];
        s_w5[e][k4 * 4 + 0] = v.x; s_w5[e][k4 * 4 + 1] = v.y;
        s_w5[e][k4 * 4 + 2] = v.z; s_w5[e][k4 * 4 + 3] = v.w;
    }
    if (tid < 64) s_b4[tid] = fc4b[tid];
    if (tid < 16) s_b5[tid] = fc5b[tid];
    if (tid < 144) s_A[tid] = Bm[tid] + Cm[tid];
    if (tid < 3)  s_t[tid] = xt[tid];
    __syncthreads();

    {
        int j = tid >> 5, lane = tid & 31;
        float a0 = 0.f, a1 = 0.f;
#pragma unroll
        for (int k = 0; k < 128; k++) {
            float f = s_f3[j][k];
            a0 = fmaf(f, s_w4[lane][k], a0);
            a1 = fmaf(f, s_w4[lane + 32][k], a1);
        }
        s_h4[j][lane]      = fmaxf(a0 + s_b4[lane], 0.f);
        s_h4[j][lane + 32] = fmaxf(a1 + s_b4[lane + 32], 0.f);
    }
    __syncthreads();

    if (tid < 128) {
        int j = tid >> 4, e = tid & 15;
        float lg = s_b5[e];
#pragma unroll
        for (int k = 0; k < 64; k++)
            lg = fmaf(s_h4[j][k], s_w5[e][k], lg);
        float mx = lg;
#pragma unroll
        for (int m = 8; m; m >>= 1)
            mx = fmaxf(mx, __shfl_xor_sync(0xffffffffu, mx, m));
        float pe = expf(lg - mx);
        float sum = pe;
#pragma unroll
        for (int m = 8; m; m >>= 1)
            sum += __shfl_xor_sync(0xffffffffu, sum, m);
        float w = pe / sum;

        int s = s0 + j;
        float d0 = s_t[0] - x[(size_t)s * 4099 + 0];
        float d1 = s_t[1] - x[(size_t)s * 4099 + 1];
        float d2 = s_t[2] - x[(size_t)s * 4099 + 2];
        const float* A = &s_A[e * 9];
        float o0 = w * (A[0] * d0 + A[1] * d1 + A[2] * d2);
        float o1 = w * (A[3] * d0 + A[4] * d1 + A[5] * d2);
        float o2 = w * (A[6] * d0 + A[7] * d1 + A[8] * d2);
#pragma unroll
        for (int m = 8; m; m >>= 1) {
            o0 += __shfl_xor_sync(0xffffffffu, o0, m);
            o1 += __shfl_xor_sync(0xffffffffu, o1, m);
            o2 += __shfl_xor_sync(0xffffffffu, o2, m);
        }
        if (e == 0) {
            out[(size_t)s * 3 + 0] = o0;
            out[(size_t)s * 3 + 1] = o1;
            out[(size_t)s * 3 + 2] = o2;
        }
    }
}

// ---------------- launch ----------------
extern "C" void kernel_launch(void* const* d_in, const int* in_sizes, int n_in,
                              void* d_out, int out_size)
{
    const float* x    = (const float*)d_in[0];
    const float* w1   = (const float*)d_in[1];
    const float* b1   = (const float*)d_in[2];
    const float* w2   = (const float*)d_in[3];
    const float* b2   = (const float*)d_in[4];
    const float* fc1w = (const float*)d_in[5];
    const float* fc1b = (const float*)d_in[6];
    const float* fc2w = (const float*)d_in[7];
    const float* fc2b = (const float*)d_in[8];
    const float* fc3w = (const float*)d_in[9];
    const float* fc3b = (const float*)d_in[10];
    const float* fc4w = (const float*)d_in[11];
    const float* fc4b = (const float*)d_in[12];
    const float* fc5w = (const float*)d_in[13];
    const float* fc5b = (const float*)d_in[14];
    const float* Bm   = (const float*)d_in[15];
    const float* Cm   = (const float*)d_in[16];
    const float* xt   = (const float*)d_in[17];

    int B = in_sizes[0] / 4099;  // 8192

    float *h2, *w1p, *f1, *f2, *f3;
    cudaGetSymbolAddress((void**)&h2,  g_h2);
    cudaGetSymbolAddress((void**)&w1p, g_w1p);
    cudaGetSymbolAddress((void**)&f1,  g_f1);
    cudaGetSymbolAddress((void**)&f2,  g_f2);
    cudaGetSymbolAddress((void**)&f3,  g_f3);

    repack_fc1<<<(512 * 1696) / 256, 256>>>(fc1w);
    fused_conv_kernel<<<B, 384>>>(x, w1, b1, w2, b2);

    gemm128_db<true><<<dim3(B / 128, 4), 256>>>(h2, 1696, w1p, 1696, fc1b, f1, 512, 1696);
    gemm128_db<true><<<dim3(B / 128, 2), 256>>>(f1, 512, fc2w, 512, fc2b, f2, 256, 512);
    gemm128_db<true><<<dim3(B / 128, 1), 256>>>(f2, 256, fc3w, 256, fc3b, f3, 128, 256);

    head2_kernel<<<B / 8, 256>>>(fc4w, fc4b, fc5w, fc5b, Bm, Cm, x, xt, (float*)d_out);
}

// round 9
// speedup vs baseline: 1.4956x; 1.1136x over previous
#include <cuda_runtime.h>
#include <cstdint>

// ---------------- scratch ----------------
__device__ float g_h2[8192 * 1696];
__device__ float g_w1p[512 * 1696];
__device__ float g_f1[8192 * 512];
__device__ float g_f2[8192 * 256];
__device__ float g_f3[8192 * 128];

// ---------------- fused conv1+pool+conv2+pool+concat ----------------
// one image per block, 480 threads. Vectorized smem loads (LDS.64 windows,
// LDS.128 padded weights).
__global__ void __launch_bounds__(480) fused_conv_kernel(
    const float* __restrict__ x,
    const float* __restrict__ w1, const float* __restrict__ b1,
    const float* __restrict__ w2, const float* __restrict__ b2)
{
    __shared__ float simg[64 * 64];          // 16 KB
    __shared__ float sh1[5 * 900];           // 18 KB
    __shared__ __align__(16) float sw1p[5 * 28];    // conv1 w, 28-padded rows
    __shared__ __align__(16) float sw2p[50 * 28];   // conv2 w, 28-padded rows
    __shared__ float sb1[5];
    __shared__ float sb2[10];
    int b = blockIdx.x;
    int tid = threadIdx.x;

    const float* xr = x + (size_t)b * 4099 + 3;
    for (int i = tid; i < 4096; i += 480) simg[i] = xr[i];
    for (int i = tid; i < 140; i += 480) {
        int ch = i / 28, q = i % 28;
        sw1p[i] = (q < 25) ? w1[ch * 25 + q] : 0.f;
    }
    for (int i = tid; i < 1400; i += 480) {
        int r = i / 28, q = i % 28;
        sw2p[i] = (q < 25) ? w2[r * 25 + q] : 0.f;
    }
    if (tid < 5)  sb1[tid] = b1[tid];
    if (tid < 10) sb2[tid] = b2[tid];
    __syncthreads();

    // ---- phase B: conv1 + relu + maxpool -> sh1[ch*900 + p]
    for (int p = tid; p < 900; p += 480) {
        int py = p / 30, px = p % 30;
        float win[6][6];
        const float* wp = &simg[(2 * py) * 64 + 2 * px];
#pragma unroll
        for (int r = 0; r < 6; r++) {
            float2 v0 = *(const float2*)(wp + r * 64);
            float2 v1 = *(const float2*)(wp + r * 64 + 2);
            float2 v2 = *(const float2*)(wp + r * 64 + 4);
            win[r][0] = v0.x; win[r][1] = v0.y;
            win[r][2] = v1.x; win[r][3] = v1.y;
            win[r][4] = v2.x; win[r][5] = v2.y;
        }
#pragma unroll
        for (int ch = 0; ch < 5; ch++) {
            float wreg[28];
#pragma unroll
            for (int q = 0; q < 7; q++) {
                float4 v = *(const float4*)&sw1p[ch * 28 + q * 4];
                wreg[q * 4 + 0] = v.x; wreg[q * 4 + 1] = v.y;
                wreg[q * 4 + 2] = v.z; wreg[q * 4 + 3] = v.w;
            }
            float a00 = 0.f, a01 = 0.f, a10 = 0.f, a11 = 0.f;
#pragma unroll
            for (int i = 0; i < 5; i++)
#pragma unroll
                for (int j = 0; j < 5; j++) {
                    float w = wreg[i * 5 + j];
                    a00 = fmaf(win[i][j],         w, a00);
                    a01 = fmaf(win[i][j + 1],     w, a01);
                    a10 = fmaf(win[i + 1][j],     w, a10);
                    a11 = fmaf(win[i + 1][j + 1], w, a11);
                }
            float m = fmaxf(fmaxf(a00, a01), fmaxf(a10, a11));
            sh1[ch * 900 + p] = fmaxf(m + sb1[ch], 0.f);
        }
    }
    __syncthreads();

    // ---- phase C: conv2 + relu + maxpool (338 threads; oc split halves)
    if (tid < 338) {
        int half = tid / 169;
        int p    = tid % 169;
        int py = p / 13, px = p % 13;
        float acc[5][4];
#pragma unroll
        for (int o = 0; o < 5; o++)
            acc[o][0] = acc[o][1] = acc[o][2] = acc[o][3] = 0.f;

#pragma unroll 1
        for (int ic = 0; ic < 5; ic++) {
            float win[6][6];
            const float* wp = &sh1[ic * 900 + (2 * py) * 30 + 2 * px];
#pragma unroll
            for (int r = 0; r < 6; r++) {
                float2 v0 = *(const float2*)(wp + r * 30);
                float2 v1 = *(const float2*)(wp + r * 30 + 2);
                float2 v2 = *(const float2*)(wp + r * 30 + 4);
                win[r][0] = v0.x; win[r][1] = v0.y;
                win[r][2] = v1.x; win[r][3] = v1.y;
                win[r][4] = v2.x; win[r][5] = v2.y;
            }
#pragma unroll
            for (int o = 0; o < 5; o++) {
                float wreg[28];
#pragma unroll
                for (int q = 0; q < 7; q++) {
                    float4 v = *(const float4*)&sw2p[((half * 5 + o) * 5 + ic) * 28 + q * 4];
                    wreg[q * 4 + 0] = v.x; wreg[q * 4 + 1] = v.y;
                    wreg[q * 4 + 2] = v.z; wreg[q * 4 + 3] = v.w;
                }
#pragma unroll
                for (int i = 0; i < 5; i++)
#pragma unroll
                    for (int j = 0; j < 5; j++) {
                        float w = wreg[i * 5 + j];
                        acc[o][0] = fmaf(win[i][j],         w, acc[o][0]);
                        acc[o][1] = fmaf(win[i][j + 1],     w, acc[o][1]);
                        acc[o][2] = fmaf(win[i + 1][j],     w, acc[o][2]);
                        acc[o][3] = fmaf(win[i + 1][j + 1], w, acc[o][3]);
                    }
            }
        }
        float* dst = &g_h2[(size_t)b * 1696];
#pragma unroll
        for (int o = 0; o < 5; o++) {
            int oc = half * 5 + o;
            float m = fmaxf(fmaxf(acc[o][0], acc[o][1]),
                            fmaxf(acc[o][2], acc[o][3]));
            dst[oc * 169 + p] = fmaxf(m + sb2[oc], 0.f);
        }
    } else if (tid < 338 + 6) {
        int j = tid - 338;
        g_h2[(size_t)b * 1696 + 1690 + j] =
            (j < 3) ? x[(size_t)b * 4099 + j] : 0.f;
    }
}

// ---------------- fc1 weight repack ----------------
__global__ void __launch_bounds__(256) repack_fc1(const float* __restrict__ w)
{
    int idx = blockIdx.x * 256 + threadIdx.x;
    int n = idx / 1696, k = idx % 1696;
    g_w1p[idx] = (k < 1693) ? w[n * 1693 + k] : 0.f;
}

// ---------------- double-buffered SGEMM, 2 blocks/SM ----------------
template <bool RELU>
__global__ void __launch_bounds__(256, 2) gemm128_db(
    const float* __restrict__ A, int lda,
    const float* __restrict__ W, int ldw,
    const float* __restrict__ bias,
    float* __restrict__ C, int ldc, int K)
{
    __shared__ float As[2][16][132];
    __shared__ float Bs[2][16][132];
    int tid = threadIdx.x;
    int m0 = blockIdx.x * 128;
    int n0 = blockIdx.y * 128;
    int tidm = tid % 16;
    int tidn = tid / 16;

    int lrow = tid >> 2;
    int lc4  = tid & 3;
    const float* aptr0 = A + (size_t)(m0 + lrow) * lda + lc4 * 4;
    const float* aptr1 = aptr0 + (size_t)64 * lda;
    const float* bptr0 = W + (size_t)(n0 + lrow) * ldw + lc4 * 4;
    const float* bptr1 = bptr0 + (size_t)64 * ldw;

    float acc[8][8];
#pragma unroll
    for (int i = 0; i < 8; i++)
#pragma unroll
        for (int j = 0; j < 8; j++) acc[i][j] = 0.f;

    float4 a0, a1, b0, b1;
    a0 = *(const float4*)(aptr0);
    a1 = *(const float4*)(aptr1);
    b0 = *(const float4*)(bptr0);
    b1 = *(const float4*)(bptr1);
    {
        float* s = &As[0][lc4 * 4][0];
        s[0 * 132 + lrow] = a0.x; s[1 * 132 + lrow] = a0.y;
        s[2 * 132 + lrow] = a0.z; s[3 * 132 + lrow] = a0.w;
        s[0 * 132 + lrow + 64] = a1.x; s[1 * 132 + lrow + 64] = a1.y;
        s[2 * 132 + lrow + 64] = a1.z; s[3 * 132 + lrow + 64] = a1.w;
        float* t = &Bs[0][lc4 * 4][0];
        t[0 * 132 + lrow] = b0.x; t[1 * 132 + lrow] = b0.y;
        t[2 * 132 + lrow] = b0.z; t[3 * 132 + lrow] = b0.w;
        t[0 * 132 + lrow + 64] = b1.x; t[1 * 132 + lrow + 64] = b1.y;
        t[2 * 132 + lrow + 64] = b1.z; t[3 * 132 + lrow + 64] = b1.w;
    }
    __syncthreads();

    int ntiles = K / 16;
    for (int t = 0; t < ntiles; t++) {
        int cur = t & 1;
        bool more = (t + 1) < ntiles;
        if (more) {
            int koff = (t + 1) * 16;
            a0 = *(const float4*)(aptr0 + koff);
            a1 = *(const float4*)(aptr1 + koff);
            b0 = *(const float4*)(bptr0 + koff);
            b1 = *(const float4*)(bptr1 + koff);
        }
#pragma unroll
        for (int kk = 0; kk < 16; kk++) {
            float ar[8], br[8];
            float4 v;
            v = *(const float4*)&As[cur][kk][tidm * 8];
            ar[0] = v.x; ar[1] = v.y; ar[2] = v.z; ar[3] = v.w;
            v = *(const float4*)&As[cur][kk][tidm * 8 + 4];
            ar[4] = v.x; ar[5] = v.y; ar[6] = v.z; ar[7] = v.w;
            v = *(const float4*)&Bs[cur][kk][tidn * 8];
            br[0] = v.x; br[1] = v.y; br[2] = v.z; br[3] = v.w;
            v = *(const float4*)&Bs[cur][kk][tidn * 8 + 4];
            br[4] = v.x; br[5] = v.y; br[6] = v.z; br[7] = v.w;
#pragma unroll
            for (int i = 0; i < 8; i++)
#pragma unroll
                for (int j = 0; j < 8; j++)
                    acc[i][j] = fmaf(ar[i], br[j], acc[i][j]);
        }
        if (more) {
            int nxt = cur ^ 1;
            float* s = &As[nxt][lc4 * 4][0];
            s[0 * 132 + lrow] = a0.x; s[1 * 132 + lrow] = a0.y;
            s[2 * 132 + lrow] = a0.z; s[3 * 132 + lrow] = a0.w;
            s[0 * 132 + lrow + 64] = a1.x; s[1 * 132 + lrow + 64] = a1.y;
            s[2 * 132 + lrow + 64] = a1.z; s[3 * 132 + lrow + 64] = a1.w;
            float* u = &Bs[nxt][lc4 * 4][0];
            u[0 * 132 + lrow] = b0.x; u[1 * 132 + lrow] = b0.y;
            u[2 * 132 + lrow] = b0.z; u[3 * 132 + lrow] = b0.w;
            u[0 * 132 + lrow + 64] = b1.x; u[1 * 132 + lrow + 64] = b1.y;
            u[2 * 132 + lrow + 64] = b1.z; u[3 * 132 + lrow + 64] = b1.w;
            __syncthreads();
        }
    }

    float bj[8];
#pragma unroll
    for (int j = 0; j < 8; j++) bj[j] = bias[n0 + tidn * 8 + j];
#pragma unroll
    for (int i = 0; i < 8; i++) {
        int row = m0 + tidm * 8 + i;
#pragma unroll
        for (int j4 = 0; j4 < 2; j4++) {
            float v0 = acc[i][j4 * 4 + 0] + bj[j4 * 4 + 0];
            float v1 = acc[i][j4 * 4 + 1] + bj[j4 * 4 + 1];
            float v2 = acc[i][j4 * 4 + 2] + bj[j4 * 4 + 2];
            float v3 = acc[i][j4 * 4 + 3] + bj[j4 * 4 + 3];
            if (RELU) {
                v0 = fmaxf(v0, 0.f); v1 = fmaxf(v1, 0.f);
                v2 = fmaxf(v2, 0.f); v3 = fmaxf(v3, 0.f);
            }
            float4 v = {v0, v1, v2, v3};
            *(float4*)&C[(size_t)row * ldc + n0 + tidn * 8 + j4 * 4] = v;
        }
    }
}

// ---------------- fused fc4 + fc5 + softmax + expert blend ----------------
__global__ void __launch_bounds__(256) head2_kernel(
    const float* __restrict__ fc4w, const float* __restrict__ fc4b,
    const float* __restrict__ fc5w, const float* __restrict__ fc5b,
    const float* __restrict__ Bm, const float* __restrict__ Cm,
    const float* __restrict__ x, const float* __restrict__ xt,
    float* __restrict__ out)
{
    __shared__ float s_w4[64][129];
    __shared__ float s_f3[8][128];
    __shared__ float s_h4[8][64];
    __shared__ float s_w5[16][65];
    __shared__ float s_b4[64];
    __shared__ float s_b5[16];
    __shared__ float s_A[144];
    __shared__ float s_t[3];
    int tid = threadIdx.x;
    int s0 = blockIdx.x * 8;

    for (int i = tid; i < 2048; i += 256) {
        int o = i >> 5, k4 = i & 31;
        float4 v = *(const float4*)&fc4w[o * 128 + k4 * 4];
        s_w4[o][k4 * 4 + 0] = v.x; s_w4[o][k4 * 4 + 1] = v.y;
        s_w4[o][k4 * 4 + 2] = v.z; s_w4[o][k4 * 4 + 3] = v.w;
    }
    {
        int j = tid >> 5, k4 = tid & 31;
        float4 v = *(const float4*)&g_f3[(size_t)(s0 + j) * 128 + k4 * 4];
        *(float4*)&s_f3[j][k4 * 4] = v;
    }
    {
        int e = tid >> 4, k4 = tid & 15;
        float4 v = *(const float4*)&fc5w[e * 64 + k4 * 4];
        s_w5[e][k4 * 4 + 0] = v.x; s_w5[e][k4 * 4 + 1] = v.y;
        s_w5[e][k4 * 4 + 2] = v.z; s_w5[e][k4 * 4 + 3] = v.w;
    }
    if (tid < 64) s_b4[tid] = fc4b[tid];
    if (tid < 16) s_b5[tid] = fc5b[tid];
    if (tid < 144) s_A[tid] = Bm[tid] + Cm[tid];
    if (tid < 3)  s_t[tid] = xt[tid];
    __syncthreads();

    {
        int j = tid >> 5, lane = tid & 31;
        float a0 = 0.f, a1 = 0.f;
#pragma unroll
        for (int k = 0; k < 128; k++) {
            float f = s_f3[j][k];
            a0 = fmaf(f, s_w4[lane][k], a0);
            a1 = fmaf(f, s_w4[lane + 32][k], a1);
        }
        s_h4[j][lane]      = fmaxf(a0 + s_b4[lane], 0.f);
        s_h4[j][lane + 32] = fmaxf(a1 + s_b4[lane + 32], 0.f);
    }
    __syncthreads();

    if (tid < 128) {
        int j = tid >> 4, e = tid & 15;
        float lg = s_b5[e];
#pragma unroll
        for (int k = 0; k < 64; k++)
            lg = fmaf(s_h4[j][k], s_w5[e][k], lg);
        float mx = lg;
#pragma unroll
        for (int m = 8; m; m >>= 1)
            mx = fmaxf(mx, __shfl_xor_sync(0xffffffffu, mx, m));
        float pe = expf(lg - mx);
        float sum = pe;
#pragma unroll
        for (int m = 8; m; m >>= 1)
            sum += __shfl_xor_sync(0xffffffffu, sum, m);
        float w = pe / sum;

        int s = s0 + j;
        float d0 = s_t[0] - x[(size_t)s * 4099 + 0];
        float d1 = s_t[1] - x[(size_t)s * 4099 + 1];
        float d2 = s_t[2] - x[(size_t)s * 4099 + 2];
        const float* A = &s_A[e * 9];
        float o0 = w * (A[0] * d0 + A[1] * d1 + A[2] * d2);
        float o1 = w * (A[3] * d0 + A[4] * d1 + A[5] * d2);
        float o2 = w * (A[6] * d0 + A[7] * d1 + A[8] * d2);
#pragma unroll
        for (int m = 8; m; m >>= 1) {
            o0 += __shfl_xor_sync(0xffffffffu, o0, m);
            o1 += __shfl_xor_sync(0xffffffffu, o1, m);
            o2 += __shfl_xor_sync(0xffffffffu, o2, m);
        }
        if (e == 0) {
            out[(size_t)s * 3 + 0] = o0;
            out[(size_t)s * 3 + 1] = o1;
            out[(size_t)s * 3 + 2] = o2;
        }
    }
}

// ---------------- launch ----------------
extern "C" void kernel_launch(void* const* d_in, const int* in_sizes, int n_in,
                              void* d_out, int out_size)
{
    const float* x    = (const float*)d_in[0];
    const float* w1   = (const float*)d_in[1];
    const float* b1   = (const float*)d_in[2];
    const float* w2   = (const float*)d_in[3];
    const float* b2   = (const float*)d_in[4];
    const float* fc1w = (const float*)d_in[5];
    const float* fc1b = (const float*)d_in[6];
    const float* fc2w = (const float*)d_in[7];
    const float* fc2b = (const float*)d_in[8];
    const float* fc3w = (const float*)d_in[9];
    const float* fc3b = (const float*)d_in[10];
    const float* fc4w = (const float*)d_in[11];
    const float* fc4b = (const float*)d_in[12];
    const float* fc5w = (const float*)d_in[13];
    const float* fc5b = (const float*)d_in[14];
    const float* Bm   = (const float*)d_in[15];
    const float* Cm   = (const float*)d_in[16];
    const float* xt   = (const float*)d_in[17];

    int B = in_sizes[0] / 4099;  // 8192

    float *h2, *w1p, *f1, *f2, *f3;
    cudaGetSymbolAddress((void**)&h2,  g_h2);
    cudaGetSymbolAddress((void**)&w1p, g_w1p);
    cudaGetSymbolAddress((void**)&f1,  g_f1);
    cudaGetSymbolAddress((void**)&f2,  g_f2);
    cudaGetSymbolAddress((void**)&f3,  g_f3);

    repack_fc1<<<(512 * 1696) / 256, 256>>>(fc1w);
    fused_conv_kernel<<<B, 480>>>(x, w1, b1, w2, b2);

    gemm128_db<true><<<dim3(B / 128, 4), 256>>>(h2, 1696, w1p, 1696, fc1b, f1, 512, 1696);
    gemm128_db<true><<<dim3(B / 128, 2), 256>>>(f1, 512, fc2w, 512, fc2b, f2, 256, 512);
    gemm128_db<true><<<dim3(B / 128, 1), 256>>>(f2, 256, fc3w, 256, fc3b, f3, 128, 256);

    head2_kernel<<<B / 8, 256>>>(fc4w, fc4b, fc5w, fc5b, Bm, Cm, x, xt, (float*)d_out);
}

// round 11
// speedup vs baseline: 1.6150x; 1.0799x over previous
#include <cuda_runtime.h>
#include <cstdint>

// ---------------- scratch ----------------
__device__ float g_h2[8192 * 1696];
__device__ float g_w1p[512 * 1696];
__device__ float g_f1[8192 * 512];
__device__ float g_f2[8192 * 256];
__device__ float g_f3[8192 * 128];

// ---------------- fused conv1+pool+conv2+pool+concat ----------------
// one image per block, 480 threads, forced 2 blocks/SM.
// Phase C uses dy-split mapping (low regs) + shfl pair-max.
__global__ void __launch_bounds__(480, 2) fused_conv_kernel(
    const float* __restrict__ x,
    const float* __restrict__ w1, const float* __restrict__ b1,
    const float* __restrict__ w2, const float* __restrict__ b2)
{
    __shared__ float simg[64 * 64];          // 16 KB
    __shared__ float sh1[5 * 900];           // 18 KB
    __shared__ __align__(16) float sw1p[5 * 28];
    __shared__ __align__(16) float sw2p[50 * 28];
    __shared__ float sb1[5];
    __shared__ float sb2[10];
    int b = blockIdx.x;
    int tid = threadIdx.x;

    const float* xr = x + (size_t)b * 4099 + 3;
    for (int i = tid; i < 4096; i += 480) simg[i] = xr[i];
    for (int i = tid; i < 140; i += 480) {
        int ch = i / 28, q = i % 28;
        sw1p[i] = (q < 25) ? w1[ch * 25 + q] : 0.f;
    }
    for (int i = tid; i < 1400; i += 480) {
        int r = i / 28, q = i % 28;
        sw2p[i] = (q < 25) ? w2[r * 25 + q] : 0.f;
    }
    if (tid < 5)  sb1[tid] = b1[tid];
    if (tid < 10) sb2[tid] = b2[tid];
    __syncthreads();

    // ---- phase B: conv1 + relu + maxpool -> sh1[ch*900 + p]
    for (int p = tid; p < 900; p += 480) {
        int py = p / 30, px = p % 30;
        float win[6][6];
        const float* wp = &simg[(2 * py) * 64 + 2 * px];
#pragma unroll
        for (int r = 0; r < 6; r++) {
            float2 v0 = *(const float2*)(wp + r * 64);
            float2 v1 = *(const float2*)(wp + r * 64 + 2);
            float2 v2 = *(const float2*)(wp + r * 64 + 4);
            win[r][0] = v0.x; win[r][1] = v0.y;
            win[r][2] = v1.x; win[r][3] = v1.y;
            win[r][4] = v2.x; win[r][5] = v2.y;
        }
#pragma unroll
        for (int ch = 0; ch < 5; ch++) {
            float a00 = 0.f, a01 = 0.f, a10 = 0.f, a11 = 0.f;
#pragma unroll
            for (int q = 0; q < 7; q++) {
                float4 wv = *(const float4*)&sw1p[ch * 28 + q * 4];
#pragma unroll
                for (int e = 0; e < 4; e++) {
                    int idx = q * 4 + e;
                    if (idx < 25) {
                        int i = idx / 5, j = idx % 5;
                        float w = (e == 0) ? wv.x : (e == 1) ? wv.y
                                : (e == 2) ? wv.z : wv.w;
                        a00 = fmaf(win[i][j],         w, a00);
                        a01 = fmaf(win[i][j + 1],     w, a01);
                        a10 = fmaf(win[i + 1][j],     w, a10);
                        a11 = fmaf(win[i + 1][j + 1], w, a11);
                    }
                }
            }
            float m = fmaxf(fmaxf(a00, a01), fmaxf(a10, a11));
            sh1[ch * 900 + p] = fmaxf(m + sb1[ch], 0.f);
        }
    }
    __syncthreads();

    // ---- phase C: conv2 + relu + maxpool, dy-split (338 threads)
    if (tid < 338) {
        int p  = tid >> 1;               // pooled pixel 0..168
        int dy = tid & 1;                // pool row
        int py = p / 13, px = p % 13;
        float acc[10][2];
#pragma unroll
        for (int o = 0; o < 10; o++) acc[o][0] = acc[o][1] = 0.f;

#pragma unroll 1
        for (int ic = 0; ic < 5; ic++) {
            float win[5][6];
            const float* wp = &sh1[ic * 900 + (2 * py + dy) * 30 + 2 * px];
#pragma unroll
            for (int r = 0; r < 5; r++) {
                float2 v0 = *(const float2*)(wp + r * 30);
                float2 v1 = *(const float2*)(wp + r * 30 + 2);
                float2 v2 = *(const float2*)(wp + r * 30 + 4);
                win[r][0] = v0.x; win[r][1] = v0.y;
                win[r][2] = v1.x; win[r][3] = v1.y;
                win[r][4] = v2.x; win[r][5] = v2.y;
            }
#pragma unroll
            for (int oc = 0; oc < 10; oc++) {
#pragma unroll
                for (int q = 0; q < 7; q++) {
                    float4 wv = *(const float4*)&sw2p[(oc * 5 + ic) * 28 + q * 4];
#pragma unroll
                    for (int e = 0; e < 4; e++) {
                        int idx = q * 4 + e;
                        if (idx < 25) {
                            int i = idx / 5, j = idx % 5;
                            float w = (e == 0) ? wv.x : (e == 1) ? wv.y
                                    : (e == 2) ? wv.z : wv.w;
                            acc[oc][0] = fmaf(win[i][j],     w, acc[oc][0]);
                            acc[oc][1] = fmaf(win[i][j + 1], w, acc[oc][1]);
                        }
                    }
                }
            }
        }
        float* dst = &g_h2[(size_t)b * 1696];
#pragma unroll
        for (int oc = 0; oc < 10; oc++) {
            float m = fmaxf(acc[oc][0], acc[oc][1]);
            m = fmaxf(m, __shfl_xor_sync(0xffffffffu, m, 1));  // pair over dy
            if (dy == 0)
                dst[oc * 169 + p] = fmaxf(m + sb2[oc], 0.f);
        }
    } else if (tid < 344) {
        int j = tid - 338;
        g_h2[(size_t)b * 1696 + 1690 + j] =
            (j < 3) ? x[(size_t)b * 4099 + j] : 0.f;
    }
}

// ---------------- fc1 weight repack ----------------
__global__ void __launch_bounds__(256) repack_fc1(const float* __restrict__ w)
{
    int idx = blockIdx.x * 256 + threadIdx.x;
    int n = idx / 1696, k = idx % 1696;
    g_w1p[idx] = (k < 1693) ? w[n * 1693 + k] : 0.f;
}

// ---------------- double-buffered SGEMM, 2 blocks/SM ----------------
template <bool RELU>
__global__ void __launch_bounds__(256, 2) gemm128_db(
    const float* __restrict__ A, int lda,
    const float* __restrict__ W, int ldw,
    const float* __restrict__ bias,
    float* __restrict__ C, int ldc, int K)
{
    __shared__ float As[2][16][132];
    __shared__ float Bs[2][16][132];
    int tid = threadIdx.x;
    int m0 = blockIdx.x * 128;
    int n0 = blockIdx.y * 128;
    int tidm = tid % 16;
    int tidn = tid / 16;

    int lrow = tid >> 2;
    int lc4  = tid & 3;
    const float* aptr0 = A + (size_t)(m0 + lrow) * lda + lc4 * 4;
    const float* aptr1 = aptr0 + (size_t)64 * lda;
    const float* bptr0 = W + (size_t)(n0 + lrow) * ldw + lc4 * 4;
    const float* bptr1 = bptr0 + (size_t)64 * ldw;

    float acc[8][8];
#pragma unroll
    for (int i = 0; i < 8; i++)
#pragma unroll
        for (int j = 0; j < 8; j++) acc[i][j] = 0.f;

    float4 a0, a1, b0, b1;
    a0 = *(const float4*)(aptr0);
    a1 = *(const float4*)(aptr1);
    b0 = *(const float4*)(bptr0);
    b1 = *(const float4*)(bptr1);
    {
        float* s = &As[0][lc4 * 4][0];
        s[0 * 132 + lrow] = a0.x; s[1 * 132 + lrow] = a0.y;
        s[2 * 132 + lrow] = a0.z; s[3 * 132 + lrow] = a0.w;
        s[0 * 132 + lrow + 64] = a1.x; s[1 * 132 + lrow + 64] = a1.y;
        s[2 * 132 + lrow + 64] = a1.z; s[3 * 132 + lrow + 64] = a1.w;
        float* t = &Bs[0][lc4 * 4][0];
        t[0 * 132 + lrow] = b0.x; t[1 * 132 + lrow] = b0.y;
        t[2 * 132 + lrow] = b0.z; t[3 * 132 + lrow] = b0.w;
        t[0 * 132 + lrow + 64] = b1.x; t[1 * 132 + lrow + 64] = b1.y;
        t[2 * 132 + lrow + 64] = b1.z; t[3 * 132 + lrow + 64] = b1.w;
    }
    __syncthreads();

    int ntiles = K / 16;
    for (int t = 0; t < ntiles; t++) {
        int cur = t & 1;
        bool more = (t + 1) < ntiles;
        if (more) {
            int koff = (t + 1) * 16;
            a0 = *(const float4*)(aptr0 + koff);
            a1 = *(const float4*)(aptr1 + koff);
            b0 = *(const float4*)(bptr0 + koff);
            b1 = *(const float4*)(bptr1 + koff);
        }
#pragma unroll
        for (int kk = 0; kk < 16; kk++) {
            float ar[8], br[8];
            float4 v;
            v = *(const float4*)&As[cur][kk][tidm * 8];
            ar[0] = v.x; ar[1] = v.y; ar[2] = v.z; ar[3] = v.w;
            v = *(const float4*)&As[cur][kk][tidm * 8 + 4];
            ar[4] = v.x; ar[5] = v.y; ar[6] = v.z; ar[7] = v.w;
            v = *(const float4*)&Bs[cur][kk][tidn * 8];
            br[0] = v.x; br[1] = v.y; br[2] = v.z; br[3] = v.w;
            v = *(const float4*)&Bs[cur][kk][tidn * 8 + 4];
            br[4] = v.x; br[5] = v.y; br[6] = v.z; br[7] = v.w;
#pragma unroll
            for (int i = 0; i < 8; i++)
#pragma unroll
                for (int j = 0; j < 8; j++)
                    acc[i][j] = fmaf(ar[i], br[j], acc[i][j]);
        }
        if (more) {
            int nxt = cur ^ 1;
            float* s = &As[nxt][lc4 * 4][0];
            s[0 * 132 + lrow] = a0.x; s[1 * 132 + lrow] = a0.y;
            s[2 * 132 + lrow] = a0.z; s[3 * 132 + lrow] = a0.w;
            s[0 * 132 + lrow + 64] = a1.x; s[1 * 132 + lrow + 64] = a1.y;
            s[2 * 132 + lrow + 64] = a1.z; s[3 * 132 + lrow + 64] = a1.w;
            float* u = &Bs[nxt][lc4 * 4][0];
            u[0 * 132 + lrow] = b0.x; u[1 * 132 + lrow] = b0.y;
            u[2 * 132 + lrow] = b0.z; u[3 * 132 + lrow] = b0.w;
            u[0 * 132 + lrow + 64] = b1.x; u[1 * 132 + lrow + 64] = b1.y;
            u[2 * 132 + lrow + 64] = b1.z; u[3 * 132 + lrow + 64] = b1.w;
            __syncthreads();
        }
    }

    float bj[8];
#pragma unroll
    for (int j = 0; j < 8; j++) bj[j] = bias[n0 + tidn * 8 + j];
#pragma unroll
    for (int i = 0; i < 8; i++) {
        int row = m0 + tidm * 8 + i;
#pragma unroll
        for (int j4 = 0; j4 < 2; j4++) {
            float v0 = acc[i][j4 * 4 + 0] + bj[j4 * 4 + 0];
            float v1 = acc[i][j4 * 4 + 1] + bj[j4 * 4 + 1];
            float v2 = acc[i][j4 * 4 + 2] + bj[j4 * 4 + 2];
            float v3 = acc[i][j4 * 4 + 3] + bj[j4 * 4 + 3];
            if (RELU) {
                v0 = fmaxf(v0, 0.f); v1 = fmaxf(v1, 0.f);
                v2 = fmaxf(v2, 0.f); v3 = fmaxf(v3, 0.f);
            }
            float4 v = {v0, v1, v2, v3};
            *(float4*)&C[(size_t)row * ldc + n0 + tidn * 8 + j4 * 4] = v;
        }
    }
}

// ---------------- fused fc4 + fc5 + softmax + expert blend ----------------
__global__ void __launch_bounds__(256) head2_kernel(
    const float* __restrict__ fc4w, const float* __restrict__ fc4b,
    const float* __restrict__ fc5w, const float* __restrict__ fc5b,
    const float* __restrict__ Bm, const float* __restrict__ Cm,
    const float* __restrict__ x, const float* __restrict__ xt,
    float* __restrict__ out)
{
    __shared__ float s_w4[64][129];
    __shared__ float s_f3[8][128];
    __shared__ float s_h4[8][64];
    __shared__ float s_w5[16][65];
    __shared__ float s_b4[64];
    __shared__ float s_b5[16];
    __shared__ float s_A[144];
    __shared__ float s_t[3];
    int tid = threadIdx.x;
    int s0 = blockIdx.x * 8;

    for (int i = tid; i < 2048; i += 256) {
        int o = i >> 5, k4 = i & 31;
        float4 v = *(const float4*)&fc4w[o * 128 + k4 * 4];
        s_w4[o][k4 * 4 + 0] = v.x; s_w4[o][k4 * 4 + 1] = v.y;
        s_w4[o][k4 * 4 + 2] = v.z; s_w4[o][k4 * 4 + 3] = v.w;
    }
    {
        int j = tid >> 5, k4 = tid & 31;
        float4 v = *(const float4*)&g_f3[(size_t)(s0 + j) * 128 + k4 * 4];
        *(float4*)&s_f3[j][k4 * 4] = v;
    }
    {
        int e = tid >> 4, k4 = tid & 15;
        float4 v = *(const float4*)&fc5w[e * 64 + k4 * 4];
        s_w5[e][k4 * 4 + 0] = v.x; s_w5[e][k4 * 4 + 1] = v.y;
        s_w5[e][k4 * 4 + 2] = v.z; s_w5[e][k4 * 4 + 3] = v.w;
    }
    if (tid < 64) s_b4[tid] = fc4b[tid];
    if (tid < 16) s_b5[tid] = fc5b[tid];
    if (tid < 144) s_A[tid] = Bm[tid] + Cm[tid];
    if (tid < 3)  s_t[tid] = xt[tid];
    __syncthreads();

    {
        int j = tid >> 5, lane = tid & 31;
        float a0 = 0.f, a1 = 0.f;
#pragma unroll
        for (int k = 0; k < 128; k++) {
            float f = s_f3[j][k];
            a0 = fmaf(f, s_w4[lane][k], a0);
            a1 = fmaf(f, s_w4[lane + 32][k], a1);
        }
        s_h4[j][lane]      = fmaxf(a0 + s_b4[lane], 0.f);
        s_h4[j][lane + 32] = fmaxf(a1 + s_b4[lane + 32], 0.f);
    }
    __syncthreads();

    if (tid < 128) {
        int j = tid >> 4, e = tid & 15;
        float lg = s_b5[e];
#pragma unroll
        for (int k = 0; k < 64; k++)
            lg = fmaf(s_h4[j][k], s_w5[e][k], lg);
        float mx = lg;
#pragma unroll
        for (int m = 8; m; m >>= 1)
            mx = fmaxf(mx, __shfl_xor_sync(0xffffffffu, mx, m));
        float pe = expf(lg - mx);
        float sum = pe;
#pragma unroll
        for (int m = 8; m; m >>= 1)
            sum += __shfl_xor_sync(0xffffffffu, sum, m);
        float w = pe / sum;

        int s = s0 + j;
        float d0 = s_t[0] - x[(size_t)s * 4099 + 0];
        float d1 = s_t[1] - x[(size_t)s * 4099 + 1];
        float d2 = s_t[2] - x[(size_t)s * 4099 + 2];
        const float* A = &s_A[e * 9];
        float o0 = w * (A[0] * d0 + A[1] * d1 + A[2] * d2);
        float o1 = w * (A[3] * d0 + A[4] * d1 + A[5] * d2);
        float o2 = w * (A[6] * d0 + A[7] * d1 + A[8] * d2);
#pragma unroll
        for (int m = 8; m; m >>= 1) {
            o0 += __shfl_xor_sync(0xffffffffu, o0, m);
            o1 += __shfl_xor_sync(0xffffffffu, o1, m);
            o2 += __shfl_xor_sync(0xffffffffu, o2, m);
        }
        if (e == 0) {
            out[(size_t)s * 3 + 0] = o0;
            out[(size_t)s * 3 + 1] = o1;
            out[(size_t)s * 3 + 2] = o2;
        }
    }
}

// ---------------- launch ----------------
extern "C" void kernel_launch(void* const* d_in, const int* in_sizes, int n_in,
                              void* d_out, int out_size)
{
    const float* x    = (const float*)d_in[0];
    const float* w1   = (const float*)d_in[1];
    const float* b1   = (const float*)d_in[2];
    const float* w2   = (const float*)d_in[3];
    const float* b2   = (const float*)d_in[4];
    const float* fc1w = (const float*)d_in[5];
    const float* fc1b = (const float*)d_in[6];
    const float* fc2w = (const float*)d_in[7];
    const float* fc2b = (const float*)d_in[8];
    const float* fc3w = (const float*)d_in[9];
    const float* fc3b = (const float*)d_in[10];
    const float* fc4w = (const float*)d_in[11];
    const float* fc4b = (const float*)d_in[12];
    const float* fc5w = (const float*)d_in[13];
    const float* fc5b = (const float*)d_in[14];
    const float* Bm   = (const float*)d_in[15];
    const float* Cm   = (const float*)d_in[16];
    const float* xt   = (const float*)d_in[17];

    int B = in_sizes[0] / 4099;  // 8192

    float *h2, *w1p, *f1, *f2, *f3;
    cudaGetSymbolAddress((void**)&h2,  g_h2);
    cudaGetSymbolAddress((void**)&w1p, g_w1p);
    cudaGetSymbolAddress((void**)&f1,  g_f1);
    cudaGetSymbolAddress((void**)&f2,  g_f2);
    cudaGetSymbolAddress((void**)&f3,  g_f3);

    repack_fc1<<<(512 * 1696) / 256, 256>>>(fc1w);
    fused_conv_kernel<<<B, 480>>>(x, w1, b1, w2, b2);

    gemm128_db<true><<<dim3(B / 128, 4), 256>>>(h2, 1696, w1p, 1696, fc1b, f1, 512, 1696);
    gemm128_db<true><<<dim3(B / 128, 2), 256>>>(f1, 512, fc2w, 512, fc2b, f2, 256, 512);
    gemm128_db<true><<<dim3(B / 128, 1), 256>>>(f2, 256, fc3w, 256, fc3b, f3, 128, 256);

    head2_kernel<<<B / 8, 256>>>(fc4w, fc4b, fc5w, fc5b, Bm, Cm, x, xt, (float*)d_out);
}

// round 12
// speedup vs baseline: 1.6177x; 1.0016x over previous
#include <cuda_runtime.h>
#include <cstdint>

// ---------------- scratch ----------------
__device__ float g_h2[8192 * 1696];
__device__ float g_w1p[512 * 1696];
__device__ float g_f1[8192 * 512];
__device__ float g_f2[8192 * 256];
__device__ float g_f3[8192 * 128];

// ---------------- fused conv1+pool+conv2+pool+concat ----------------
// one image per block, 480 threads, forced 2 blocks/SM.
// Phase C uses dy-split mapping (low regs) + shfl pair-max.
__global__ void __launch_bounds__(480, 2) fused_conv_kernel(
    const float* __restrict__ x,
    const float* __restrict__ w1, const float* __restrict__ b1,
    const float* __restrict__ w2, const float* __restrict__ b2)
{
    __shared__ float simg[64 * 64];          // 16 KB
    __shared__ float sh1[5 * 900];           // 18 KB
    __shared__ __align__(16) float sw1p[5 * 28];
    __shared__ __align__(16) float sw2p[50 * 28];
    __shared__ float sb1[5];
    __shared__ float sb2[10];
    int b = blockIdx.x;
    int tid = threadIdx.x;

    const float* xr = x + (size_t)b * 4099 + 3;
    for (int i = tid; i < 4096; i += 480) simg[i] = xr[i];
    for (int i = tid; i < 140; i += 480) {
        int ch = i / 28, q = i % 28;
        sw1p[i] = (q < 25) ? w1[ch * 25 + q] : 0.f;
    }
    for (int i = tid; i < 1400; i += 480) {
        int r = i / 28, q = i % 28;
        sw2p[i] = (q < 25) ? w2[r * 25 + q] : 0.f;
    }
    if (tid < 5)  sb1[tid] = b1[tid];
    if (tid < 10) sb2[tid] = b2[tid];
    __syncthreads();

    // ---- phase B: conv1 + relu + maxpool -> sh1[ch*900 + p]
    for (int p = tid; p < 900; p += 480) {
        int py = p / 30, px = p % 30;
        float win[6][6];
        const float* wp = &simg[(2 * py) * 64 + 2 * px];
#pragma unroll
        for (int r = 0; r < 6; r++) {
            float2 v0 = *(const float2*)(wp + r * 64);
            float2 v1 = *(const float2*)(wp + r * 64 + 2);
            float2 v2 = *(const float2*)(wp + r * 64 + 4);
            win[r][0] = v0.x; win[r][1] = v0.y;
            win[r][2] = v1.x; win[r][3] = v1.y;
            win[r][4] = v2.x; win[r][5] = v2.y;
        }
#pragma unroll
        for (int ch = 0; ch < 5; ch++) {
            float a00 = 0.f, a01 = 0.f, a10 = 0.f, a11 = 0.f;
#pragma unroll
            for (int q = 0; q < 7; q++) {
                float4 wv = *(const float4*)&sw1p[ch * 28 + q * 4];
#pragma unroll
                for (int e = 0; e < 4; e++) {
                    int idx = q * 4 + e;
                    if (idx < 25) {
                        int i = idx / 5, j = idx % 5;
                        float w = (e == 0) ? wv.x : (e == 1) ? wv.y
                                : (e == 2) ? wv.z : wv.w;
                        a00 = fmaf(win[i][j],         w, a00);
                        a01 = fmaf(win[i][j + 1],     w, a01);
                        a10 = fmaf(win[i + 1][j],     w, a10);
                        a11 = fmaf(win[i + 1][j + 1], w, a11);
                    }
                }
            }
            float m = fmaxf(fmaxf(a00, a01), fmaxf(a10, a11));
            sh1[ch * 900 + p] = fmaxf(m + sb1[ch], 0.f);
        }
    }
    __syncthreads();

    // ---- phase C: conv2 + relu + maxpool, dy-split (338 threads)
    if (tid < 338) {
        int p  = tid >> 1;               // pooled pixel 0..168
        int dy = tid & 1;                // pool row
        int py = p / 13, px = p % 13;
        float acc[10][2];
#pragma unroll
        for (int o = 0; o < 10; o++) acc[o][0] = acc[o][1] = 0.f;

#pragma unroll 1
        for (int ic = 0; ic < 5; ic++) {
            float win[5][6];
            const float* wp = &sh1[ic * 900 + (2 * py + dy) * 30 + 2 * px];
#pragma unroll
            for (int r = 0; r < 5; r++) {
                float2 v0 = *(const float2*)(wp + r * 30);
                float2 v1 = *(const float2*)(wp + r * 30 + 2);
                float2 v2 = *(const float2*)(wp + r * 30 + 4);
                win[r][0] = v0.x; win[r][1] = v0.y;
                win[r][2] = v1.x; win[r][3] = v1.y;
                win[r][4] = v2.x; win[r][5] = v2.y;
            }
#pragma unroll
            for (int oc = 0; oc < 10; oc++) {
#pragma unroll
                for (int q = 0; q < 7; q++) {
                    float4 wv = *(const float4*)&sw2p[(oc * 5 + ic) * 28 + q * 4];
#pragma unroll
                    for (int e = 0; e < 4; e++) {
                        int idx = q * 4 + e;
                        if (idx < 25) {
                            int i = idx / 5, j = idx % 5;
                            float w = (e == 0) ? wv.x : (e == 1) ? wv.y
                                    : (e == 2) ? wv.z : wv.w;
                            acc[oc][0] = fmaf(win[i][j],     w, acc[oc][0]);
                            acc[oc][1] = fmaf(win[i][j + 1], w, acc[oc][1]);
                        }
                    }
                }
            }
        }
        float* dst = &g_h2[(size_t)b * 1696];
#pragma unroll
        for (int oc = 0; oc < 10; oc++) {
            float m = fmaxf(acc[oc][0], acc[oc][1]);
            m = fmaxf(m, __shfl_xor_sync(0xffffffffu, m, 1));  // pair over dy
            if (dy == 0)
                dst[oc * 169 + p] = fmaxf(m + sb2[oc], 0.f);
        }
    } else if (tid < 344) {
        int j = tid - 338;
        g_h2[(size_t)b * 1696 + 1690 + j] =
            (j < 3) ? x[(size_t)b * 4099 + j] : 0.f;
    }
}

// ---------------- fc1 weight repack ----------------
__global__ void __launch_bounds__(256) repack_fc1(const float* __restrict__ w)
{
    int idx = blockIdx.x * 256 + threadIdx.x;
    int n = idx / 1696, k = idx % 1696;
    g_w1p[idx] = (k < 1693) ? w[n * 1693 + k] : 0.f;
}

// ---------------- double-buffered SGEMM, 2 blocks/SM ----------------
template <bool RELU>
__global__ void __launch_bounds__(256, 2) gemm128_db(
    const float* __restrict__ A, int lda,
    const float* __restrict__ W, int ldw,
    const float* __restrict__ bias,
    float* __restrict__ C, int ldc, int K)
{
    __shared__ float As[2][16][132];
    __shared__ float Bs[2][16][132];
    int tid = threadIdx.x;
    int m0 = blockIdx.x * 128;
    int n0 = blockIdx.y * 128;
    int tidm = tid % 16;
    int tidn = tid / 16;

    int lrow = tid >> 2;
    int lc4  = tid & 3;
    const float* aptr0 = A + (size_t)(m0 + lrow) * lda + lc4 * 4;
    const float* aptr1 = aptr0 + (size_t)64 * lda;
    const float* bptr0 = W + (size_t)(n0 + lrow) * ldw + lc4 * 4;
    const float* bptr1 = bptr0 + (size_t)64 * ldw;

    float acc[8][8];
#pragma unroll
    for (int i = 0; i < 8; i++)
#pragma unroll
        for (int j = 0; j < 8; j++) acc[i][j] = 0.f;

    float4 a0, a1, b0, b1;
    a0 = *(const float4*)(aptr0);
    a1 = *(const float4*)(aptr1);
    b0 = *(const float4*)(bptr0);
    b1 = *(const float4*)(bptr1);
    {
        float* s = &As[0][lc4 * 4][0];
        s[0 * 132 + lrow] = a0.x; s[1 * 132 + lrow] = a0.y;
        s[2 * 132 + lrow] = a0.z; s[3 * 132 + lrow] = a0.w;
        s[0 * 132 + lrow + 64] = a1.x; s[1 * 132 + lrow + 64] = a1.y;
        s[2 * 132 + lrow + 64] = a1.z; s[3 * 132 + lrow + 64] = a1.w;
        float* t = &Bs[0][lc4 * 4][0];
        t[0 * 132 + lrow] = b0.x; t[1 * 132 + lrow] = b0.y;
        t[2 * 132 + lrow] = b0.z; t[3 * 132 + lrow] = b0.w;
        t[0 * 132 + lrow + 64] = b1.x; t[1 * 132 + lrow + 64] = b1.y;
        t[2 * 132 + lrow + 64] = b1.z; t[3 * 132 + lrow + 64] = b1.w;
    }
    __syncthreads();

    int ntiles = K / 16;
    for (int t = 0; t < ntiles; t++) {
        int cur = t & 1;
        bool more = (t + 1) < ntiles;
        if (more) {
            int koff = (t + 1) * 16;
            a0 = *(const float4*)(aptr0 + koff);
            a1 = *(const float4*)(aptr1 + koff);
            b0 = *(const float4*)(bptr0 + koff);
            b1 = *(const float4*)(bptr1 + koff);
        }
#pragma unroll
        for (int kk = 0; kk < 16; kk++) {
            float ar[8], br[8];
            float4 v;
            v = *(const float4*)&As[cur][kk][tidm * 8];
            ar[0] = v.x; ar[1] = v.y; ar[2] = v.z; ar[3] = v.w;
            v = *(const float4*)&As[cur][kk][tidm * 8 + 4];
            ar[4] = v.x; ar[5] = v.y; ar[6] = v.z; ar[7] = v.w;
            v = *(const float4*)&Bs[cur][kk][tidn * 8];
            br[0] = v.x; br[1] = v.y; br[2] = v.z; br[3] = v.w;
            v = *(const float4*)&Bs[cur][kk][tidn * 8 + 4];
            br[4] = v.x; br[5] = v.y; br[6] = v.z; br[7] = v.w;
#pragma unroll
            for (int i = 0; i < 8; i++)
#pragma unroll
                for (int j = 0; j < 8; j++)
                    acc[i][j] = fmaf(ar[i], br[j], acc[i][j]);
        }
        if (more) {
            int nxt = cur ^ 1;
            float* s = &As[nxt][lc4 * 4][0];
            s[0 * 132 + lrow] = a0.x; s[1 * 132 + lrow] = a0.y;
            s[2 * 132 + lrow] = a0.z; s[3 * 132 + lrow] = a0.w;
            s[0 * 132 + lrow + 64] = a1.x; s[1 * 132 + lrow + 64] = a1.y;
            s[2 * 132 + lrow + 64] = a1.z; s[3 * 132 + lrow + 64] = a1.w;
            float* u = &Bs[nxt][lc4 * 4][0];
            u[0 * 132 + lrow] = b0.x; u[1 * 132 + lrow] = b0.y;
            u[2 * 132 + lrow] = b0.z; u[3 * 132 + lrow] = b0.w;
            u[0 * 132 + lrow + 64] = b1.x; u[1 * 132 + lrow + 64] = b1.y;
            u[2 * 132 + lrow + 64] = b1.z; u[3 * 132 + lrow + 64] = b1.w;
            __syncthreads();
        }
    }

    float bj[8];
#pragma unroll
    for (int j = 0; j < 8; j++) bj[j] = bias[n0 + tidn * 8 + j];
#pragma unroll
    for (int i = 0; i < 8; i++) {
        int row = m0 + tidm * 8 + i;
#pragma unroll
        for (int j4 = 0; j4 < 2; j4++) {
            float v0 = acc[i][j4 * 4 + 0] + bj[j4 * 4 + 0];
            float v1 = acc[i][j4 * 4 + 1] + bj[j4 * 4 + 1];
            float v2 = acc[i][j4 * 4 + 2] + bj[j4 * 4 + 2];
            float v3 = acc[i][j4 * 4 + 3] + bj[j4 * 4 + 3];
            if (RELU) {
                v0 = fmaxf(v0, 0.f); v1 = fmaxf(v1, 0.f);
                v2 = fmaxf(v2, 0.f); v3 = fmaxf(v3, 0.f);
            }
            float4 v = {v0, v1, v2, v3};
            *(float4*)&C[(size_t)row * ldc + n0 + tidn * 8 + j4 * 4] = v;
        }
    }
}

// ---------------- fused fc4 + fc5 + softmax + expert blend ----------------
__global__ void __launch_bounds__(256) head2_kernel(
    const float* __restrict__ fc4w, const float* __restrict__ fc4b,
    const float* __restrict__ fc5w, const float* __restrict__ fc5b,
    const float* __restrict__ Bm, const float* __restrict__ Cm,
    const float* __restrict__ x, const float* __restrict__ xt,
    float* __restrict__ out)
{
    __shared__ float s_w4[64][129];
    __shared__ float s_f3[8][128];
    __shared__ float s_h4[8][64];
    __shared__ float s_w5[16][65];
    __shared__ float s_b4[64];
    __shared__ float s_b5[16];
    __shared__ float s_A[144];
    __shared__ float s_t[3];
    int tid = threadIdx.x;
    int s0 = blockIdx.x * 8;

    for (int i = tid; i < 2048; i += 256) {
        int o = i >> 5, k4 = i & 31;
        float4 v = *(const float4*)&fc4w[o * 128 + k4 * 4];
        s_w4[o][k4 * 4 + 0] = v.x; s_w4[o][k4 * 4 + 1] = v.y;
        s_w4[o][k4 * 4 + 2] = v.z; s_w4[o][k4 * 4 + 3] = v.w;
    }
    {
        int j = tid >> 5, k4 = tid & 31;
        float4 v = *(const float4*)&g_f3[(size_t)(s0 + j) * 128 + k4 * 4];
        *(float4*)&s_f3[j][k4 * 4] = v;
    }
    {
        int e = tid >> 4, k4 = tid & 15;
        float4 v = *(const float4*)&fc5w[e * 64 + k4 * 4];
        s_w5[e][k4 * 4 + 0] = v.x; s_w5[e][k4 * 4 + 1] = v.y;
        s_w5[e][k4 * 4 + 2] = v.z; s_w5[e][k4 * 4 + 3] = v.w;
    }
    if (tid < 64) s_b4[tid] = fc4b[tid];
    if (tid < 16) s_b5[tid] = fc5b[tid];
    if (tid < 144) s_A[tid] = Bm[tid] + Cm[tid];
    if (tid < 3)  s_t[tid] = xt[tid];
    __syncthreads();

    {
        int j = tid >> 5, lane = tid & 31;
        float a0 = 0.f, a1 = 0.f;
#pragma unroll
        for (int k = 0; k < 128; k++) {
            float f = s_f3[j][k];
            a0 = fmaf(f, s_w4[lane][k], a0);
            a1 = fmaf(f, s_w4[lane + 32][k], a1);
        }
        s_h4[j][lane]      = fmaxf(a0 + s_b4[lane], 0.f);
        s_h4[j][lane + 32] = fmaxf(a1 + s_b4[lane + 32], 0.f);
    }
    __syncthreads();

    if (tid < 128) {
        int j = tid >> 4, e = tid & 15;
        float lg = s_b5[e];
#pragma unroll
        for (int k = 0; k < 64; k++)
            lg = fmaf(s_h4[j][k], s_w5[e][k], lg);
        float mx = lg;
#pragma unroll
        for (int m = 8; m; m >>= 1)
            mx = fmaxf(mx, __shfl_xor_sync(0xffffffffu, mx, m));
        float pe = expf(lg - mx);
        float sum = pe;
#pragma unroll
        for (int m = 8; m; m >>= 1)
            sum += __shfl_xor_sync(0xffffffffu, sum, m);
        float w = pe / sum;

        int s = s0 + j;
        float d0 = s_t[0] - x[(size_t)s * 4099 + 0];
        float d1 = s_t[1] - x[(size_t)s * 4099 + 1];
        float d2 = s_t[2] - x[(size_t)s * 4099 + 2];
        const float* A = &s_A[e * 9];
        float o0 = w * (A[0] * d0 + A[1] * d1 + A[2] * d2);
        float o1 = w * (A[3] * d0 + A[4] * d1 + A[5] * d2);
        float o2 = w * (A[6] * d0 + A[7] * d1 + A[8] * d2);
#pragma unroll
        for (int m = 8; m; m >>= 1) {
            o0 += __shfl_xor_sync(0xffffffffu, o0, m);
            o1 += __shfl_xor_sync(0xffffffffu, o1, m);
            o2 += __shfl_xor_sync(0xffffffffu, o2, m);
        }
        if (e == 0) {
            out[(size_t)s * 3 + 0] = o0;
            out[(size_t)s * 3 + 1] = o1;
            out[(size_t)s * 3 + 2] = o2;
        }
    }
}

// ---------------- launch ----------------
extern "C" void kernel_launch(void* const* d_in, const int* in_sizes, int n_in,
                              void* d_out, int out_size)
{
    const float* x    = (const float*)d_in[0];
    const float* w1   = (const float*)d_in[1];
    const float* b1   = (const float*)d_in[2];
    const float* w2   = (const float*)d_in[3];
    const float* b2   = (const float*)d_in[4];
    const float* fc1w = (const float*)d_in[5];
    const float* fc1b = (const float*)d_in[6];
    const float* fc2w = (const float*)d_in[7];
    const float* fc2b = (const float*)d_in[8];
    const float* fc3w = (const float*)d_in[9];
    const float* fc3b = (const float*)d_in[10];
    const float* fc4w = (const float*)d_in[11];
    const float* fc4b = (const float*)d_in[12];
    const float* fc5w = (const float*)d_in[13];
    const float* fc5b = (const float*)d_in[14];
    const float* Bm   = (const float*)d_in[15];
    const float* Cm   = (const float*)d_in[16];
    const float* xt   = (const float*)d_in[17];

    int B = in_sizes[0] / 4099;  // 8192

    float *h2, *w1p, *f1, *f2, *f3;
    cudaGetSymbolAddress((void**)&h2,  g_h2);
    cudaGetSymbolAddress((void**)&w1p, g_w1p);
    cudaGetSymbolAddress((void**)&f1,  g_f1);
    cudaGetSymbolAddress((void**)&f2,  g_f2);
    cudaGetSymbolAddress((void**)&f3,  g_f3);

    repack_fc1<<<(512 * 1696) / 256, 256>>>(fc1w);
    fused_conv_kernel<<<B, 480>>>(x, w1, b1, w2, b2);

    gemm128_db<true><<<dim3(B / 128, 4), 256>>>(h2, 1696, w1p, 1696, fc1b, f1, 512, 1696);
    gemm128_db<true><<<dim3(B / 128, 2), 256>>>(f1, 512, fc2w, 512, fc2b, f2, 256, 512);
    gemm128_db<true><<<dim3(B / 128, 1), 256>>>(f2, 256, fc3w, 256, fc3b, f3, 128, 256);

    head2_kernel<<<B / 8, 256>>>(fc4w, fc4b, fc5w, fc5b, Bm, Cm, x, xt, (float*)d_out);
}